// round 5
// baseline (speedup 1.0000x reference)
#include <cuda_runtime.h>
#include <cstdint>

#define NUM_USER     200000
#define NUM_QUESTION 20000
#define NC           128
#define DH           512
#define H2           256
#define BATCH        16384
#define MAXE         384
#define LDS_         36   // smem row stride (floats): conflict-free fragment access

// ---------------- scratch (__device__ globals) ----------------
__device__ float g_SP [BATCH * NC];
__device__ float g_SCP[BATCH * MAXE];
__device__ float g_SCN[BATCH * MAXE];
__device__ float g_Bm [BATCH * NC];
__device__ float g_Disc[BATCH];
__device__ float g_A  [BATCH * NC];
__device__ float g_U  [BATCH * DH];
__device__ float g_X  [BATCH * DH];
__device__ float g_H  [BATCH * H2];

struct EdgeExp { unsigned char lp[MAXE]; };
struct GraphP  { unsigned char lp[NC]; unsigned char pred[NC][3]; };

__device__ __forceinline__ float sigmoidf(float x) {
    return __fdividef(1.0f, 1.0f + __expf(-x));
}
__device__ __forceinline__ uint32_t f2tf(float f) {
    uint32_t r;
    asm("cvt.rna.tf32.f32 %0, %1;" : "=r"(r) : "f"(f));
    return r;
}
__device__ __forceinline__ void mma_tf32(float c[4],
                                         uint32_t a0, uint32_t a1, uint32_t a2, uint32_t a3,
                                         uint32_t b0, uint32_t b1) {
    asm volatile(
        "mma.sync.aligned.m16n8k8.row.col.f32.tf32.tf32.f32 "
        "{%0,%1,%2,%3}, {%4,%5,%6,%7}, {%8,%9}, {%0,%1,%2,%3};"
        : "+f"(c[0]), "+f"(c[1]), "+f"(c[2]), "+f"(c[3])
        : "r"(a0), "r"(a1), "r"(a2), "r"(a3), "r"(b0), "r"(b1));
}

// ---------------- K0: elementwise transforms ----------------
__global__ void k_elem(const int* __restrict__ uid, const int* __restrict__ qid,
                       const float* __restrict__ priori,
                       const float* __restrict__ condi_p, const float* __restrict__ condi_n,
                       const float* __restrict__ idiff, const float* __restrict__ idisc,
                       const float* __restrict__ qt,
                       EdgeExp ee, int E)
{
    int b   = blockIdx.y;
    int idx = blockIdx.x * blockDim.x + threadIdx.x;
    int total = 2 * NC + 2 * E + 1;
    if (idx >= total) return;
    if (idx < NC) {
        int u = uid[b];
        g_SP[b * NC + idx] = sigmoidf(priori[(size_t)u * NC + idx]);
    } else if (idx < NC + 2 * E) {
        int u = uid[b];
        int j = idx - NC;
        bool isP = (j < E);
        if (!isP) j -= E;
        const float* src = isP ? condi_p : condi_n;
        float v = sigmoidf(src[(size_t)u * E + j]);
        int l = ee.lp[j];
        if (l == 2)      v = sqrtf(v);
        else if (l == 3) v = __powf(v, 0.33333334f);
        float* dst = isP ? g_SCP : g_SCN;
        dst[(size_t)b * E + j] = v;
    } else if (idx < 2 * NC + 2 * E) {
        int q = qid[b];
        int k = idx - NC - 2 * E;
        g_Bm[b * NC + k] = sigmoidf(idiff[(size_t)q * NC + k]) * qt[(size_t)q * NC + k];
    } else {
        int q = qid[b];
        g_Disc[b] = sigmoidf(idisc[q]);
    }
}

// ---------------- K1: sequential posterior chain ----------------
__global__ void k_mastery(const int* __restrict__ qid, const float* __restrict__ qt,
                          GraphP g, int E)
{
    int b = blockIdx.x * blockDim.x + threadIdx.x;
    if (b >= BATCH) return;
    const float* sp  = g_SP  + b * NC;
    const float* scp = g_SCP + (size_t)b * E;
    const float* scn = g_SCN + (size_t)b * E;
    float m[NC];
    int off = 0;
    #pragma unroll 1
    for (int k = 0; k < NC; k++) {
        int l = g.lp[k];
        float v;
        if (l == 0) {
            v = sp[k];
        } else {
            v = 1.0f;
            #pragma unroll 1
            for (int j = 0; j < l; j++) {
                float mp = m[g.pred[k][j]];
                v *= scp[off + j] * mp + scn[off + j] * (1.0f - mp);
            }
            off += l;
        }
        m[k] = v;
    }
    int q = qid[b];
    const float* qr = qt + (size_t)q * NC;
    float* a = g_A + b * NC;
    #pragma unroll 4
    for (int k = 0; k < NC; k++) a[k] = m[k] * qr[k];
}

// ---------------- pipelined tf32-MMA GEMM ----------------
// CTA 128x128, BK=32, 8 warps (2M x 4N), warp tile 64x32, 4x4 m16n8k8 frags.
// 2-stage smem double buffer; LDG(ch+1) issued before MMA(ch), STS after.
// EPI 0: g_U = g_A  @ Wu^T               (raw store)
// EPI 1: g_X = (tanh(g_U+bu) - sigmoid(g_Bm@Wi^T + bi)) * disc
// EPI 2: g_H = sigmoid(g_X @ W1^T + b1)
#define STAGE_F   (2 * 128 * LDS_)          // floats per stage (A tile + W tile)
#define SMEM_GEMM (2 * STAGE_F * 4)         // 73728 bytes

__device__ __forceinline__ void ldg_chunk(float4 pA[4], float4 pW[4],
                                          const float* __restrict__ A,
                                          const float* __restrict__ W,
                                          int lda, int t)
{
    #pragma unroll
    for (int i = 0; i < 4; i++) {
        int idx = t + i * 256;
        int r = idx >> 3, c = (idx & 7) * 4;
        pA[i] = *(const float4*)(A + (size_t)r * lda + c);
        pW[i] = *(const float4*)(W + (size_t)r * lda + c);
    }
}
__device__ __forceinline__ void sts_chunk(uint32_t* sA, uint32_t* sW,
                                          const float4 pA[4], const float4 pW[4], int t)
{
    #pragma unroll
    for (int i = 0; i < 4; i++) {
        int idx = t + i * 256;
        int r = idx >> 3, c = (idx & 7) * 4;
        sA[r * LDS_ + c]     = f2tf(pA[i].x); sA[r * LDS_ + c + 1] = f2tf(pA[i].y);
        sA[r * LDS_ + c + 2] = f2tf(pA[i].z); sA[r * LDS_ + c + 3] = f2tf(pA[i].w);
        sW[r * LDS_ + c]     = f2tf(pW[i].x); sW[r * LDS_ + c + 1] = f2tf(pW[i].y);
        sW[r * LDS_ + c + 2] = f2tf(pW[i].z); sW[r * LDS_ + c + 3] = f2tf(pW[i].w);
    }
}

template<int LDA, int EPI>
__global__ void __launch_bounds__(256) gemm_pipe(const float* __restrict__ W,
                                                 const float* __restrict__ bias,
                                                 const float* __restrict__ bias2)
{
    const float* A; float* OUT; int ldout;
    if      (EPI == 0) { A = g_A;  OUT = g_U; ldout = DH; }
    else if (EPI == 1) { A = g_Bm; OUT = g_X; ldout = DH; }
    else               { A = g_X;  OUT = g_H; ldout = H2; }

    extern __shared__ uint32_t smx[];
    int t = threadIdx.x, lane = t & 31, warp = t >> 5;
    int wm = (warp & 1) * 64;
    int wn = (warp >> 1) * 32;
    int m0 = blockIdx.x * 128, n0 = blockIdx.y * 128;
    int g   = lane >> 2;
    int tig = lane & 3;

    const float* Ab = A + (size_t)m0 * LDA;
    const float* Wb = W + (size_t)n0 * LDA;

    float acc[4][4][4];
    #pragma unroll
    for (int mi = 0; mi < 4; mi++)
        #pragma unroll
        for (int ni = 0; ni < 4; ni++)
            #pragma unroll
            for (int q = 0; q < 4; q++) acc[mi][ni][q] = 0.f;

    const int NCH = LDA / 32;
    float4 pA[4], pW[4];

    // prologue: fill stage 0
    ldg_chunk(pA, pW, Ab, Wb, LDA, t);
    sts_chunk(smx, smx + 128 * LDS_, pA, pW, t);
    __syncthreads();

    #pragma unroll
    for (int ch = 0; ch < NCH; ch++) {
        if (ch + 1 < NCH)
            ldg_chunk(pA, pW, Ab + (ch + 1) * 32, Wb + (ch + 1) * 32, LDA, t);

        uint32_t* sA = smx + (ch & 1) * STAGE_F;
        uint32_t* sW = sA + 128 * LDS_;
        #pragma unroll
        for (int kk = 0; kk < 4; kk++) {
            int kb = kk * 8;
            uint32_t bf[4][2];
            #pragma unroll
            for (int ni = 0; ni < 4; ni++) {
                int n = wn + ni * 8 + g;
                bf[ni][0] = sW[n * LDS_ + kb + tig];
                bf[ni][1] = sW[n * LDS_ + kb + tig + 4];
            }
            #pragma unroll
            for (int mi = 0; mi < 4; mi++) {
                int r = wm + mi * 16 + g;
                uint32_t a0 = sA[r * LDS_ + kb + tig];
                uint32_t a1 = sA[(r + 8) * LDS_ + kb + tig];
                uint32_t a2 = sA[r * LDS_ + kb + tig + 4];
                uint32_t a3 = sA[(r + 8) * LDS_ + kb + tig + 4];
                #pragma unroll
                for (int ni = 0; ni < 4; ni++)
                    mma_tf32(acc[mi][ni], a0, a1, a2, a3, bf[ni][0], bf[ni][1]);
            }
        }
        if (ch + 1 < NCH) {
            uint32_t* dA = smx + ((ch + 1) & 1) * STAGE_F;
            sts_chunk(dA, dA + 128 * LDS_, pA, pW, t);
        }
        __syncthreads();
    }

    // epilogue
    #pragma unroll
    for (int mi = 0; mi < 4; mi++) {
        int r0 = m0 + wm + mi * 16 + g;
        float d0 = 0.f, d1 = 0.f;
        if (EPI == 1) { d0 = g_Disc[r0]; d1 = g_Disc[r0 + 8]; }
        #pragma unroll
        for (int ni = 0; ni < 4; ni++) {
            int col = n0 + wn + ni * 8 + tig * 2;
            float2 o0, o1;
            if (EPI == 0) {
                o0.x = acc[mi][ni][0]; o0.y = acc[mi][ni][1];
                o1.x = acc[mi][ni][2]; o1.y = acc[mi][ni][3];
            } else if (EPI == 1) {
                float bu0 = bias[col], bu1 = bias[col + 1];
                float bi0 = bias2[col], bi1 = bias2[col + 1];
                float2 u0 = *(const float2*)(g_U + (size_t)r0 * DH + col);
                float2 u1 = *(const float2*)(g_U + (size_t)(r0 + 8) * DH + col);
                o0.x = (tanhf(u0.x + bu0) - sigmoidf(acc[mi][ni][0] + bi0)) * d0;
                o0.y = (tanhf(u0.y + bu1) - sigmoidf(acc[mi][ni][1] + bi1)) * d0;
                o1.x = (tanhf(u1.x + bu0) - sigmoidf(acc[mi][ni][2] + bi0)) * d1;
                o1.y = (tanhf(u1.y + bu1) - sigmoidf(acc[mi][ni][3] + bi1)) * d1;
            } else {
                float b0 = bias[col], b1v = bias[col + 1];
                o0.x = sigmoidf(acc[mi][ni][0] + b0);
                o0.y = sigmoidf(acc[mi][ni][1] + b1v);
                o1.x = sigmoidf(acc[mi][ni][2] + b0);
                o1.y = sigmoidf(acc[mi][ni][3] + b1v);
            }
            *(float2*)(OUT + (size_t)r0 * ldout + col)       = o0;
            *(float2*)(OUT + (size_t)(r0 + 8) * ldout + col) = o1;
        }
    }
}

// ---------------- K4: final GEMV + sigmoid ----------------
__global__ void k_out(const float* __restrict__ W2, const float* __restrict__ b2,
                      float* __restrict__ out)
{
    int gw   = (blockIdx.x * blockDim.x + threadIdx.x) >> 5;
    int lane = threadIdx.x & 31;
    if (gw >= BATCH) return;
    const float4* h4 = (const float4*)(g_H + (size_t)gw * H2);
    const float4* w4 = (const float4*)W2;
    float s = 0.f;
    #pragma unroll
    for (int i = 0; i < 2; i++) {
        float4 hv = h4[lane + i * 32], wv = w4[lane + i * 32];
        s += hv.x * wv.x + hv.y * wv.y + hv.z * wv.z + hv.w * wv.w;
    }
    #pragma unroll
    for (int o = 16; o; o >>= 1) s += __shfl_xor_sync(0xffffffffu, s, o);
    if (lane == 0) out[gw] = sigmoidf(s + b2[0]);
}

// ---------------- host: numpy-legacy MT19937 graph reconstruction ----------------
namespace {
struct MT { uint32_t mt[624]; int idx; };
static void mt_seed(MT& s, uint32_t seed) {
    s.mt[0] = seed;
    for (int i = 1; i < 624; i++)
        s.mt[i] = 1812433253u * (s.mt[i-1] ^ (s.mt[i-1] >> 30)) + (uint32_t)i;
    s.idx = 624;
}
static uint32_t mt_next(MT& s) {
    if (s.idx >= 624) {
        for (int i = 0; i < 624; i++) {
            uint32_t y = (s.mt[i] & 0x80000000u) | (s.mt[(i+1) % 624] & 0x7fffffffu);
            s.mt[i] = s.mt[(i+397) % 624] ^ (y >> 1) ^ ((y & 1u) ? 0x9908b0dfu : 0u);
        }
        s.idx = 0;
    }
    uint32_t y = s.mt[s.idx++];
    y ^= y >> 11;
    y ^= (y << 7)  & 0x9d2c5680u;
    y ^= (y << 15) & 0xefc60000u;
    y ^= y >> 18;
    return y;
}
static uint32_t draw_bounded(MT& s, uint32_t rng) {
    uint32_t mask = rng; mask |= mask >> 1; mask |= mask >> 2; mask |= mask >> 4;
    mask |= mask >> 8; mask |= mask >> 16;
    uint32_t v;
    do { v = mt_next(s) & mask; } while (v > rng);
    return v;
}
static void build_graph(GraphP& gp, EdgeExp& ee, int& E) {
    MT mt; mt_seed(mt, 0u);
    int off = 0;
    for (int k = 0; k < NC; k++) {
        int l = 0;
        if (k > 0) {
            int hi = (k < 3 ? k : 3) + 1;
            l = (int)draw_bounded(mt, (uint32_t)(hi - 1));
        }
        int preds[3] = {0, 0, 0};
        if (l > 0) {
            int arr[NC];
            for (int i = 0; i < k; i++) arr[i] = i;
            for (int i = k - 1; i >= 1; i--) {
                uint32_t j = draw_bounded(mt, (uint32_t)i);
                int tmp = arr[i]; arr[i] = arr[(int)j]; arr[(int)j] = tmp;
            }
            for (int jj = 0; jj < l; jj++) preds[jj] = arr[jj];
            for (int a = 0; a < l; a++)
                for (int b2_ = a + 1; b2_ < l; b2_++)
                    if (preds[b2_] < preds[a]) { int tm = preds[a]; preds[a] = preds[b2_]; preds[b2_] = tm; }
        }
        gp.lp[k] = (unsigned char)l;
        for (int jj = 0; jj < 3; jj++) gp.pred[k][jj] = (unsigned char)(jj < l ? preds[jj] : 0);
        for (int jj = 0; jj < l; jj++) ee.lp[off + jj] = (unsigned char)l;
        off += l;
    }
    E = off;
}
} // namespace

extern "C" void kernel_launch(void* const* d_in, const int* in_sizes, int n_in,
                              void* d_out, int out_size)
{
    GraphP gp; EdgeExp ee; int E;
    build_graph(gp, ee, E);

    const int*   uid    = (const int*)  d_in[0];
    const int*   qid    = (const int*)  d_in[1];
    const float* priori = (const float*)d_in[2];
    const float* cpd    = (const float*)d_in[3];
    const float* cnd    = (const float*)d_in[4];
    const float* idiff  = (const float*)d_in[5];
    const float* idisc  = (const float*)d_in[6];
    const float* qt     = (const float*)d_in[7];
    const float* Wu     = (const float*)d_in[8];
    const float* bu     = (const float*)d_in[9];
    const float* Wi     = (const float*)d_in[10];
    const float* bi     = (const float*)d_in[11];
    const float* W1     = (const float*)d_in[12];
    const float* b1     = (const float*)d_in[13];
    const float* W2     = (const float*)d_in[14];
    const float* b2     = (const float*)d_in[15];
    float* out = (float*)d_out;

    int Ein = in_sizes[3] / NUM_USER;
    if (Ein > 0 && Ein <= MAXE) E = Ein;

    static bool attr_done = false;
    if (!attr_done) {
        cudaFuncSetAttribute(gemm_pipe<128, 0>, cudaFuncAttributeMaxDynamicSharedMemorySize, SMEM_GEMM);
        cudaFuncSetAttribute(gemm_pipe<128, 1>, cudaFuncAttributeMaxDynamicSharedMemorySize, SMEM_GEMM);
        cudaFuncSetAttribute(gemm_pipe<512, 2>, cudaFuncAttributeMaxDynamicSharedMemorySize, SMEM_GEMM);
        attr_done = true;
    }

    int total = 2 * NC + 2 * E + 1;
    dim3 g0((total + 255) / 256, BATCH);
    k_elem<<<g0, 256>>>(uid, qid, priori, cpd, cnd, idiff, idisc, qt, ee, E);

    k_mastery<<<(BATCH + 127) / 128, 128>>>(qid, qt, gp, E);

    gemm_pipe<128, 0><<<dim3(BATCH / 128, DH / 128), 256, SMEM_GEMM>>>(Wu, nullptr, nullptr);
    gemm_pipe<128, 1><<<dim3(BATCH / 128, DH / 128), 256, SMEM_GEMM>>>(Wi, bu, bi);
    gemm_pipe<512, 2><<<dim3(BATCH / 128, H2 / 128), 256, SMEM_GEMM>>>(W1, b1, nullptr);

    k_out<<<(BATCH * 32 + 255) / 256, 256>>>(W2, b2, out);
}

// round 6
// speedup vs baseline: 1.1258x; 1.1258x over previous
#include <cuda_runtime.h>
#include <cstdint>

#define NUM_USER     200000
#define NUM_QUESTION 20000
#define NC           128
#define DH           512
#define H2           256
#define BATCH        16384
#define MAXE         384
#define LDS_         36                 // smem row stride (floats)
#define TILEF        (128 * LDS_)       // floats per tile
#define STAGEF       (2 * TILEF)        // A + W tiles per stage
#define SMEM_GEMM    (2 * STAGEF * 4)   // 73728 bytes (2 stages)

// ---------------- scratch (__device__ globals) ----------------
__device__ float g_SP [BATCH * NC];
__device__ float g_SCP[BATCH * MAXE];
__device__ float g_SCN[BATCH * MAXE];
__device__ float g_Bm [BATCH * NC];
__device__ float g_Disc[BATCH];
__device__ float g_A  [BATCH * NC];
__device__ float g_U  [BATCH * DH];
__device__ float g_X  [BATCH * DH];
__device__ float g_H  [BATCH * H2];
__device__ float g_Wu [DH * NC];
__device__ float g_Wi [DH * NC];
__device__ float g_W1 [H2 * DH];

struct EdgeExp { unsigned char lp[MAXE]; };
struct GraphP  { unsigned char lp[NC]; unsigned char pred[NC][3]; };

__device__ __forceinline__ float sigmoidf(float x) {
    return __fdividef(1.0f, 1.0f + __expf(-x));
}
// round fp32 -> tf32 representation (kept in fp32 bits)
__device__ __forceinline__ float tf32f(float x) {
    uint32_t r;
    asm("cvt.rna.tf32.f32 %0, %1;" : "=r"(r) : "f"(x));
    return __uint_as_float(r);
}
__device__ __forceinline__ uint32_t smem_u32(const void* p) {
    uint32_t a;
    asm("{ .reg .u64 t; cvta.to.shared.u64 t, %1; cvt.u32.u64 %0, t; }" : "=r"(a) : "l"(p));
    return a;
}
__device__ __forceinline__ void cp16(uint32_t s, const void* g) {
    asm volatile("cp.async.cg.shared.global [%0], [%1], 16;" :: "r"(s), "l"(g));
}
__device__ __forceinline__ void cp_commit() {
    asm volatile("cp.async.commit_group;" ::: "memory");
}
__device__ __forceinline__ void cp_wait0() {
    asm volatile("cp.async.wait_group 0;" ::: "memory");
}
__device__ __forceinline__ void mma_tf32(float c[4],
                                         uint32_t a0, uint32_t a1, uint32_t a2, uint32_t a3,
                                         uint32_t b0, uint32_t b1) {
    asm volatile(
        "mma.sync.aligned.m16n8k8.row.col.f32.tf32.tf32.f32 "
        "{%0,%1,%2,%3}, {%4,%5,%6,%7}, {%8,%9}, {%0,%1,%2,%3};"
        : "+f"(c[0]), "+f"(c[1]), "+f"(c[2]), "+f"(c[3])
        : "r"(a0), "r"(a1), "r"(a2), "r"(a3), "r"(b0), "r"(b1));
}

// ---------------- K-1: pre-round weights to tf32 ----------------
__global__ void k_prep(const float* __restrict__ Wu, const float* __restrict__ Wi,
                       const float* __restrict__ W1)
{
    int i = blockIdx.x * blockDim.x + threadIdx.x;
    if (i < DH * NC) {
        g_Wu[i] = tf32f(Wu[i]);
        g_Wi[i] = tf32f(Wi[i]);
    }
    if (i < H2 * DH) g_W1[i] = tf32f(W1[i]);
}

// ---------------- K0: elementwise transforms ----------------
__global__ void k_elem(const int* __restrict__ uid, const int* __restrict__ qid,
                       const float* __restrict__ priori,
                       const float* __restrict__ condi_p, const float* __restrict__ condi_n,
                       const float* __restrict__ idiff, const float* __restrict__ idisc,
                       const float* __restrict__ qt,
                       EdgeExp ee, int E)
{
    int b   = blockIdx.y;
    int idx = blockIdx.x * blockDim.x + threadIdx.x;
    int total = 2 * NC + 2 * E + 1;
    if (idx >= total) return;
    if (idx < NC) {
        int u = uid[b];
        g_SP[b * NC + idx] = sigmoidf(priori[(size_t)u * NC + idx]);
    } else if (idx < NC + 2 * E) {
        int u = uid[b];
        int j = idx - NC;
        bool isP = (j < E);
        if (!isP) j -= E;
        const float* src = isP ? condi_p : condi_n;
        float v = sigmoidf(src[(size_t)u * E + j]);
        int l = ee.lp[j];
        if (l == 2)      v = sqrtf(v);
        else if (l == 3) v = __powf(v, 0.33333334f);
        float* dst = isP ? g_SCP : g_SCN;
        dst[(size_t)b * E + j] = v;
    } else if (idx < 2 * NC + 2 * E) {
        int q = qid[b];
        int k = idx - NC - 2 * E;
        g_Bm[b * NC + k] = tf32f(sigmoidf(idiff[(size_t)q * NC + k]) * qt[(size_t)q * NC + k]);
    } else {
        int q = qid[b];
        g_Disc[b] = sigmoidf(idisc[q]);
    }
}

// ---------------- K1: sequential posterior chain ----------------
__global__ void k_mastery(const int* __restrict__ qid, const float* __restrict__ qt,
                          GraphP g, int E)
{
    int b = blockIdx.x * blockDim.x + threadIdx.x;
    if (b >= BATCH) return;
    const float* sp  = g_SP  + b * NC;
    const float* scp = g_SCP + (size_t)b * E;
    const float* scn = g_SCN + (size_t)b * E;
    float m[NC];
    int off = 0;
    #pragma unroll 1
    for (int k = 0; k < NC; k++) {
        int l = g.lp[k];
        float v;
        if (l == 0) {
            v = sp[k];
        } else {
            v = 1.0f;
            #pragma unroll 1
            for (int j = 0; j < l; j++) {
                float mp = m[g.pred[k][j]];
                v *= scp[off + j] * mp + scn[off + j] * (1.0f - mp);
            }
            off += l;
        }
        m[k] = v;
    }
    int q = qid[b];
    const float* qr = qt + (size_t)q * NC;
    float* a = g_A + b * NC;
    #pragma unroll 4
    for (int k = 0; k < NC; k++) a[k] = tf32f(m[k] * qr[k]);
}

// ---------------- cp.async-pipelined tf32-MMA GEMM ----------------
// CTA 128x128, BK=32, 8 warps (2M x 4N), warp tile 64x32, 4x4 m16n8k8 frags.
// Operands pre-rounded to tf32 at producers; hot loop = cp.async + LDS + HMMA.
// EPI 0: g_U = g_A  @ g_Wu^T            (raw store)
// EPI 1: g_X = (tanh(g_U+bu) - sigmoid(g_Bm@g_Wi^T + bi)) * disc   (g_X tf32-rounded)
// EPI 2: g_H = sigmoid(g_X @ g_W1^T + b1)
template<int LDA, int EPI>
__global__ void __launch_bounds__(256, 2) gemm_cp(const float* __restrict__ bias,
                                                  const float* __restrict__ bias2)
{
    const float* A; const float* W; float* OUT; int ldout;
    if      (EPI == 0) { A = g_A;  W = g_Wu; OUT = g_U; ldout = DH; }
    else if (EPI == 1) { A = g_Bm; W = g_Wi; OUT = g_X; ldout = DH; }
    else               { A = g_X;  W = g_W1; OUT = g_H; ldout = H2; }

    extern __shared__ uint32_t smx[];
    int t = threadIdx.x, lane = t & 31, warp = t >> 5;
    int wm = (warp & 1) * 64;
    int wn = (warp >> 1) * 32;
    int m0 = blockIdx.x * 128, n0 = blockIdx.y * 128;
    int g   = lane >> 2;
    int tig = lane & 3;

    const float* Ab = A + (size_t)m0 * LDA;
    const float* Wb = W + (size_t)n0 * LDA;

    // each thread copies 4x16B per tile; thread -> (row, col4) for cp.async
    int cr = t >> 3;             // base row 0..31 (x4 via +32*i)
    int cc = (t & 7) * 4;        // float col 0..28

    float acc[4][4][4];
    #pragma unroll
    for (int mi = 0; mi < 4; mi++)
        #pragma unroll
        for (int ni = 0; ni < 4; ni++)
            #pragma unroll
            for (int q = 0; q < 4; q++) acc[mi][ni][q] = 0.f;

    const int NCH = LDA / 32;

    // prologue: stage 0
    {
        uint32_t sA = smem_u32(smx), sW = smem_u32(smx + TILEF);
        #pragma unroll
        for (int i = 0; i < 4; i++) {
            int r = cr + i * 32;
            cp16(sA + (r * LDS_ + cc) * 4, Ab + (size_t)r * LDA + cc);
            cp16(sW + (r * LDS_ + cc) * 4, Wb + (size_t)r * LDA + cc);
        }
        cp_commit();
    }

    #pragma unroll 2
    for (int ch = 0; ch < NCH; ch++) {
        cp_wait0();
        __syncthreads();
        if (ch + 1 < NCH) {
            uint32_t* st = smx + ((ch + 1) & 1) * STAGEF;
            uint32_t sA = smem_u32(st), sW = smem_u32(st + TILEF);
            const float* Ac = Ab + (ch + 1) * 32;
            const float* Wc = Wb + (ch + 1) * 32;
            #pragma unroll
            for (int i = 0; i < 4; i++) {
                int r = cr + i * 32;
                cp16(sA + (r * LDS_ + cc) * 4, Ac + (size_t)r * LDA + cc);
                cp16(sW + (r * LDS_ + cc) * 4, Wc + (size_t)r * LDA + cc);
            }
            cp_commit();
        }
        uint32_t* sA = smx + (ch & 1) * STAGEF;
        uint32_t* sW = sA + TILEF;
        #pragma unroll
        for (int kk = 0; kk < 4; kk++) {
            int kb = kk * 8;
            uint32_t bf[4][2];
            #pragma unroll
            for (int ni = 0; ni < 4; ni++) {
                int n = wn + ni * 8 + g;
                bf[ni][0] = sW[n * LDS_ + kb + tig];
                bf[ni][1] = sW[n * LDS_ + kb + tig + 4];
            }
            #pragma unroll
            for (int mi = 0; mi < 4; mi++) {
                int r = wm + mi * 16 + g;
                uint32_t a0 = sA[r * LDS_ + kb + tig];
                uint32_t a1 = sA[(r + 8) * LDS_ + kb + tig];
                uint32_t a2 = sA[r * LDS_ + kb + tig + 4];
                uint32_t a3 = sA[(r + 8) * LDS_ + kb + tig + 4];
                #pragma unroll
                for (int ni = 0; ni < 4; ni++)
                    mma_tf32(acc[mi][ni], a0, a1, a2, a3, bf[ni][0], bf[ni][1]);
            }
        }
    }

    // epilogue
    #pragma unroll
    for (int mi = 0; mi < 4; mi++) {
        int r0 = m0 + wm + mi * 16 + g;
        float d0 = 0.f, d1 = 0.f;
        if (EPI == 1) { d0 = g_Disc[r0]; d1 = g_Disc[r0 + 8]; }
        #pragma unroll
        for (int ni = 0; ni < 4; ni++) {
            int col = n0 + wn + ni * 8 + tig * 2;
            float2 o0, o1;
            if (EPI == 0) {
                o0.x = acc[mi][ni][0]; o0.y = acc[mi][ni][1];
                o1.x = acc[mi][ni][2]; o1.y = acc[mi][ni][3];
            } else if (EPI == 1) {
                float bu0 = bias[col], bu1 = bias[col + 1];
                float bi0 = bias2[col], bi1 = bias2[col + 1];
                float2 u0 = *(const float2*)(g_U + (size_t)r0 * DH + col);
                float2 u1 = *(const float2*)(g_U + (size_t)(r0 + 8) * DH + col);
                o0.x = tf32f((tanhf(u0.x + bu0) - sigmoidf(acc[mi][ni][0] + bi0)) * d0);
                o0.y = tf32f((tanhf(u0.y + bu1) - sigmoidf(acc[mi][ni][1] + bi1)) * d0);
                o1.x = tf32f((tanhf(u1.x + bu0) - sigmoidf(acc[mi][ni][2] + bi0)) * d1);
                o1.y = tf32f((tanhf(u1.y + bu1) - sigmoidf(acc[mi][ni][3] + bi1)) * d1);
            } else {
                float b0 = bias[col], b1v = bias[col + 1];
                o0.x = sigmoidf(acc[mi][ni][0] + b0);
                o0.y = sigmoidf(acc[mi][ni][1] + b1v);
                o1.x = sigmoidf(acc[mi][ni][2] + b0);
                o1.y = sigmoidf(acc[mi][ni][3] + b1v);
            }
            *(float2*)(OUT + (size_t)r0 * ldout + col)       = o0;
            *(float2*)(OUT + (size_t)(r0 + 8) * ldout + col) = o1;
        }
    }
}

// ---------------- K4: final GEMV + sigmoid ----------------
__global__ void k_out(const float* __restrict__ W2, const float* __restrict__ b2,
                      float* __restrict__ out)
{
    int gw   = (blockIdx.x * blockDim.x + threadIdx.x) >> 5;
    int lane = threadIdx.x & 31;
    if (gw >= BATCH) return;
    const float4* h4 = (const float4*)(g_H + (size_t)gw * H2);
    const float4* w4 = (const float4*)W2;
    float s = 0.f;
    #pragma unroll
    for (int i = 0; i < 2; i++) {
        float4 hv = h4[lane + i * 32], wv = w4[lane + i * 32];
        s += hv.x * wv.x + hv.y * wv.y + hv.z * wv.z + hv.w * wv.w;
    }
    #pragma unroll
    for (int o = 16; o; o >>= 1) s += __shfl_xor_sync(0xffffffffu, s, o);
    if (lane == 0) out[gw] = sigmoidf(s + b2[0]);
}

// ---------------- host: numpy-legacy MT19937 graph reconstruction ----------------
namespace {
struct MT { uint32_t mt[624]; int idx; };
static void mt_seed(MT& s, uint32_t seed) {
    s.mt[0] = seed;
    for (int i = 1; i < 624; i++)
        s.mt[i] = 1812433253u * (s.mt[i-1] ^ (s.mt[i-1] >> 30)) + (uint32_t)i;
    s.idx = 624;
}
static uint32_t mt_next(MT& s) {
    if (s.idx >= 624) {
        for (int i = 0; i < 624; i++) {
            uint32_t y = (s.mt[i] & 0x80000000u) | (s.mt[(i+1) % 624] & 0x7fffffffu);
            s.mt[i] = s.mt[(i+397) % 624] ^ (y >> 1) ^ ((y & 1u) ? 0x9908b0dfu : 0u);
        }
        s.idx = 0;
    }
    uint32_t y = s.mt[s.idx++];
    y ^= y >> 11;
    y ^= (y << 7)  & 0x9d2c5680u;
    y ^= (y << 15) & 0xefc60000u;
    y ^= y >> 18;
    return y;
}
static uint32_t draw_bounded(MT& s, uint32_t rng) {
    uint32_t mask = rng; mask |= mask >> 1; mask |= mask >> 2; mask |= mask >> 4;
    mask |= mask >> 8; mask |= mask >> 16;
    uint32_t v;
    do { v = mt_next(s) & mask; } while (v > rng);
    return v;
}
static void build_graph(GraphP& gp, EdgeExp& ee, int& E) {
    MT mt; mt_seed(mt, 0u);
    int off = 0;
    for (int k = 0; k < NC; k++) {
        int l = 0;
        if (k > 0) {
            int hi = (k < 3 ? k : 3) + 1;
            l = (int)draw_bounded(mt, (uint32_t)(hi - 1));
        }
        int preds[3] = {0, 0, 0};
        if (l > 0) {
            int arr[NC];
            for (int i = 0; i < k; i++) arr[i] = i;
            for (int i = k - 1; i >= 1; i--) {
                uint32_t j = draw_bounded(mt, (uint32_t)i);
                int tmp = arr[i]; arr[i] = arr[(int)j]; arr[(int)j] = tmp;
            }
            for (int jj = 0; jj < l; jj++) preds[jj] = arr[jj];
            for (int a = 0; a < l; a++)
                for (int b2_ = a + 1; b2_ < l; b2_++)
                    if (preds[b2_] < preds[a]) { int tm = preds[a]; preds[a] = preds[b2_]; preds[b2_] = tm; }
        }
        gp.lp[k] = (unsigned char)l;
        for (int jj = 0; jj < 3; jj++) gp.pred[k][jj] = (unsigned char)(jj < l ? preds[jj] : 0);
        for (int jj = 0; jj < l; jj++) ee.lp[off + jj] = (unsigned char)l;
        off += l;
    }
    E = off;
}
} // namespace

extern "C" void kernel_launch(void* const* d_in, const int* in_sizes, int n_in,
                              void* d_out, int out_size)
{
    GraphP gp; EdgeExp ee; int E;
    build_graph(gp, ee, E);

    const int*   uid    = (const int*)  d_in[0];
    const int*   qid    = (const int*)  d_in[1];
    const float* priori = (const float*)d_in[2];
    const float* cpd    = (const float*)d_in[3];
    const float* cnd    = (const float*)d_in[4];
    const float* idiff  = (const float*)d_in[5];
    const float* idisc  = (const float*)d_in[6];
    const float* qt     = (const float*)d_in[7];
    const float* Wu     = (const float*)d_in[8];
    const float* bu     = (const float*)d_in[9];
    const float* Wi     = (const float*)d_in[10];
    const float* bi     = (const float*)d_in[11];
    const float* W1     = (const float*)d_in[12];
    const float* b1     = (const float*)d_in[13];
    const float* W2     = (const float*)d_in[14];
    const float* b2     = (const float*)d_in[15];
    float* out = (float*)d_out;

    int Ein = in_sizes[3] / NUM_USER;
    if (Ein > 0 && Ein <= MAXE) E = Ein;

    static bool attr_done = false;
    if (!attr_done) {
        cudaFuncSetAttribute(gemm_cp<128, 0>, cudaFuncAttributeMaxDynamicSharedMemorySize, SMEM_GEMM);
        cudaFuncSetAttribute(gemm_cp<128, 1>, cudaFuncAttributeMaxDynamicSharedMemorySize, SMEM_GEMM);
        cudaFuncSetAttribute(gemm_cp<512, 2>, cudaFuncAttributeMaxDynamicSharedMemorySize, SMEM_GEMM);
        attr_done = true;
    }

    k_prep<<<(H2 * DH + 255) / 256, 256>>>(Wu, Wi, W1);

    int total = 2 * NC + 2 * E + 1;
    dim3 g0((total + 255) / 256, BATCH);
    k_elem<<<g0, 256>>>(uid, qid, priori, cpd, cnd, idiff, idisc, qt, ee, E);

    k_mastery<<<(BATCH + 127) / 128, 128>>>(qid, qt, gp, E);

    gemm_cp<128, 0><<<dim3(BATCH / 128, DH / 128), 256, SMEM_GEMM>>>(nullptr, nullptr);
    gemm_cp<128, 1><<<dim3(BATCH / 128, DH / 128), 256, SMEM_GEMM>>>(bu, bi);
    gemm_cp<512, 2><<<dim3(BATCH / 128, H2 / 128), 256, SMEM_GEMM>>>(b1, nullptr);

    k_out<<<(BATCH * 32 + 255) / 256, 256>>>(W2, b2, out);
}

// round 7
// speedup vs baseline: 1.5960x; 1.4177x over previous
#include <cuda_runtime.h>
#include <cstdint>

#define NUM_USER     200000
#define NUM_QUESTION 20000
#define NC           128
#define DH           512
#define H2           256
#define BATCH        16384
#define MAXE         384
#define LDS_         36                 // smem row stride (floats)
#define TILEF        (128 * LDS_)       // floats per tile
#define STAGEF       (2 * TILEF)        // A + W tiles per stage
#define SMEM_GEMM    (2 * STAGEF * 4)   // 73728 bytes (2 stages)

// ---------------- scratch (__device__ globals) ----------------
__device__ float g_Bm [BATCH * NC];
__device__ float g_Disc[BATCH];
__device__ float g_A  [BATCH * NC];
__device__ float g_U  [BATCH * DH];
__device__ float g_X  [BATCH * DH];
__device__ float g_H  [BATCH * H2];
__device__ float g_Wu [DH * NC];
__device__ float g_Wi [DH * NC];
__device__ float g_W1 [H2 * DH];

// level schedule, passed by value
struct Sched {
    unsigned char  order[NC];      // concepts sorted by level
    unsigned char  lp[NC];         // #preds per concept
    unsigned short off[NC];        // edge offset per concept
    unsigned char  pred[NC][3];
    float          invl[NC];       // 1/lp (lp>0)
    short          lvlStart[NC + 1];
    int            nLvl;
};

__device__ __forceinline__ float sigmoidf(float x) {
    return __fdividef(1.0f, 1.0f + __expf(-x));
}
__device__ __forceinline__ float tf32f(float x) {
    uint32_t r;
    asm("cvt.rna.tf32.f32 %0, %1;" : "=r"(r) : "f"(x));
    return __uint_as_float(r);
}
__device__ __forceinline__ uint32_t smem_u32(const void* p) {
    uint32_t a;
    asm("{ .reg .u64 t; cvta.to.shared.u64 t, %1; cvt.u32.u64 %0, t; }" : "=r"(a) : "l"(p));
    return a;
}
__device__ __forceinline__ void cp16(uint32_t s, const void* g) {
    asm volatile("cp.async.cg.shared.global [%0], [%1], 16;" :: "r"(s), "l"(g));
}
__device__ __forceinline__ void cp_commit() {
    asm volatile("cp.async.commit_group;" ::: "memory");
}
__device__ __forceinline__ void cp_wait0() {
    asm volatile("cp.async.wait_group 0;" ::: "memory");
}
__device__ __forceinline__ void mma_tf32(float c[4],
                                         uint32_t a0, uint32_t a1, uint32_t a2, uint32_t a3,
                                         uint32_t b0, uint32_t b1) {
    asm volatile(
        "mma.sync.aligned.m16n8k8.row.col.f32.tf32.tf32.f32 "
        "{%0,%1,%2,%3}, {%4,%5,%6,%7}, {%8,%9}, {%0,%1,%2,%3};"
        : "+f"(c[0]), "+f"(c[1]), "+f"(c[2]), "+f"(c[3])
        : "r"(a0), "r"(a1), "r"(a2), "r"(a3), "r"(b0), "r"(b1));
}

// ---------------- K-1: pre-round weights to tf32 ----------------
__global__ void k_prep(const float* __restrict__ Wu, const float* __restrict__ Wi,
                       const float* __restrict__ W1)
{
    int i = blockIdx.x * blockDim.x + threadIdx.x;
    if (i < DH * NC) {
        g_Wu[i] = tf32f(Wu[i]);
        g_Wi[i] = tf32f(Wi[i]);
    }
    if (i < H2 * DH) g_W1[i] = tf32f(W1[i]);
}

// ---------------- K0: Bm / disc only ----------------
__global__ void k_elem2(const int* __restrict__ qid,
                        const float* __restrict__ idiff, const float* __restrict__ idisc,
                        const float* __restrict__ qt)
{
    int idx = blockIdx.x * blockDim.x + threadIdx.x;
    if (idx >= BATCH * NC) return;
    int b = idx >> 7, k = idx & 127;
    int q = qid[b];
    g_Bm[idx] = tf32f(sigmoidf(idiff[(size_t)q * NC + k]) * qt[(size_t)q * NC + k]);
    if (k == 0) g_Disc[b] = sigmoidf(idisc[q]);
}

// ---------------- K1: fused warp-per-row level-parallel posterior ----------------
// 8 warps/block, warp w handles row b. Per-warp smem: cp/cn sigmoid rows + m[].
#define WPB 8
__global__ void __launch_bounds__(WPB * 32) k_mastery2(
    const int* __restrict__ uid, const int* __restrict__ qid,
    const float* __restrict__ priori,
    const float* __restrict__ condi_p, const float* __restrict__ condi_n,
    const float* __restrict__ qt, Sched s, int E)
{
    __shared__ float sm_m [WPB][NC];
    __shared__ float sm_cp[WPB][MAXE];
    __shared__ float sm_cn[WPB][MAXE];

    int lane = threadIdx.x & 31, w = threadIdx.x >> 5;
    int b = blockIdx.x * WPB + w;
    int u = uid[b];

    const float* cpr = condi_p + (size_t)u * E;
    const float* cnr = condi_n + (size_t)u * E;
    for (int j = lane; j < E; j += 32) {
        sm_cp[w][j] = sigmoidf(cpr[j]);
        sm_cn[w][j] = sigmoidf(cnr[j]);
    }
    __syncwarp();

    const float* pr = priori + (size_t)u * NC;
    for (int lv = 0; lv < s.nLvl; lv++) {
        int e = s.lvlStart[lv + 1];
        for (int i = s.lvlStart[lv] + lane; i < e; i += 32) {
            int k = s.order[i];
            int l = s.lp[k];
            float v;
            if (l == 0) {
                v = sigmoidf(pr[k]);
            } else {
                int o = s.off[k];
                float inv = s.invl[k];
                v = 1.0f;
                #pragma unroll 1
                for (int j = 0; j < l; j++) {
                    float mp = sm_m[w][s.pred[k][j]];
                    float a = sm_cp[w][o + j], bb = sm_cn[w][o + j];
                    if (l > 1) { a = __powf(a, inv); bb = __powf(bb, inv); }
                    v *= a * mp + bb * (1.0f - mp);
                }
            }
            sm_m[w][k] = v;
        }
        __syncwarp();
    }

    int q = qid[b];
    const float* qr = qt + (size_t)q * NC;
    float* ao = g_A + (size_t)b * NC;
    for (int k = lane; k < NC; k += 32)
        ao[k] = tf32f(sm_m[w][k] * qr[k]);
}

// ---------------- cp.async-pipelined tf32-MMA GEMM ----------------
template<int LDA, int EPI>
__global__ void __launch_bounds__(256, 2) gemm_cp(const float* __restrict__ bias,
                                                  const float* __restrict__ bias2)
{
    const float* A; const float* W; float* OUT; int ldout;
    if      (EPI == 0) { A = g_A;  W = g_Wu; OUT = g_U; ldout = DH; }
    else if (EPI == 1) { A = g_Bm; W = g_Wi; OUT = g_X; ldout = DH; }
    else               { A = g_X;  W = g_W1; OUT = g_H; ldout = H2; }

    extern __shared__ uint32_t smx[];
    int t = threadIdx.x, lane = t & 31, warp = t >> 5;
    int wm = (warp & 1) * 64;
    int wn = (warp >> 1) * 32;
    int m0 = blockIdx.x * 128, n0 = blockIdx.y * 128;
    int g   = lane >> 2;
    int tig = lane & 3;

    const float* Ab = A + (size_t)m0 * LDA;
    const float* Wb = W + (size_t)n0 * LDA;

    int cr = t >> 3;
    int cc = (t & 7) * 4;

    float acc[4][4][4];
    #pragma unroll
    for (int mi = 0; mi < 4; mi++)
        #pragma unroll
        for (int ni = 0; ni < 4; ni++)
            #pragma unroll
            for (int q = 0; q < 4; q++) acc[mi][ni][q] = 0.f;

    const int NCH = LDA / 32;

    {
        uint32_t sA = smem_u32(smx), sW = smem_u32(smx + TILEF);
        #pragma unroll
        for (int i = 0; i < 4; i++) {
            int r = cr + i * 32;
            cp16(sA + (r * LDS_ + cc) * 4, Ab + (size_t)r * LDA + cc);
            cp16(sW + (r * LDS_ + cc) * 4, Wb + (size_t)r * LDA + cc);
        }
        cp_commit();
    }

    #pragma unroll 2
    for (int ch = 0; ch < NCH; ch++) {
        cp_wait0();
        __syncthreads();
        if (ch + 1 < NCH) {
            uint32_t* st = smx + ((ch + 1) & 1) * STAGEF;
            uint32_t sA = smem_u32(st), sW = smem_u32(st + TILEF);
            const float* Ac = Ab + (ch + 1) * 32;
            const float* Wc = Wb + (ch + 1) * 32;
            #pragma unroll
            for (int i = 0; i < 4; i++) {
                int r = cr + i * 32;
                cp16(sA + (r * LDS_ + cc) * 4, Ac + (size_t)r * LDA + cc);
                cp16(sW + (r * LDS_ + cc) * 4, Wc + (size_t)r * LDA + cc);
            }
            cp_commit();
        }
        uint32_t* sA = smx + (ch & 1) * STAGEF;
        uint32_t* sW = sA + TILEF;
        #pragma unroll
        for (int kk = 0; kk < 4; kk++) {
            int kb = kk * 8;
            uint32_t bf[4][2];
            #pragma unroll
            for (int ni = 0; ni < 4; ni++) {
                int n = wn + ni * 8 + g;
                bf[ni][0] = sW[n * LDS_ + kb + tig];
                bf[ni][1] = sW[n * LDS_ + kb + tig + 4];
            }
            #pragma unroll
            for (int mi = 0; mi < 4; mi++) {
                int r = wm + mi * 16 + g;
                uint32_t a0 = sA[r * LDS_ + kb + tig];
                uint32_t a1 = sA[(r + 8) * LDS_ + kb + tig];
                uint32_t a2 = sA[r * LDS_ + kb + tig + 4];
                uint32_t a3 = sA[(r + 8) * LDS_ + kb + tig + 4];
                #pragma unroll
                for (int ni = 0; ni < 4; ni++)
                    mma_tf32(acc[mi][ni], a0, a1, a2, a3, bf[ni][0], bf[ni][1]);
            }
        }
    }

    #pragma unroll
    for (int mi = 0; mi < 4; mi++) {
        int r0 = m0 + wm + mi * 16 + g;
        float d0 = 0.f, d1 = 0.f;
        if (EPI == 1) { d0 = g_Disc[r0]; d1 = g_Disc[r0 + 8]; }
        #pragma unroll
        for (int ni = 0; ni < 4; ni++) {
            int col = n0 + wn + ni * 8 + tig * 2;
            float2 o0, o1;
            if (EPI == 0) {
                o0.x = acc[mi][ni][0]; o0.y = acc[mi][ni][1];
                o1.x = acc[mi][ni][2]; o1.y = acc[mi][ni][3];
            } else if (EPI == 1) {
                float bu0 = bias[col], bu1 = bias[col + 1];
                float bi0 = bias2[col], bi1 = bias2[col + 1];
                float2 u0 = *(const float2*)(g_U + (size_t)r0 * DH + col);
                float2 u1 = *(const float2*)(g_U + (size_t)(r0 + 8) * DH + col);
                o0.x = tf32f((tanhf(u0.x + bu0) - sigmoidf(acc[mi][ni][0] + bi0)) * d0);
                o0.y = tf32f((tanhf(u0.y + bu1) - sigmoidf(acc[mi][ni][1] + bi1)) * d0);
                o1.x = tf32f((tanhf(u1.x + bu0) - sigmoidf(acc[mi][ni][2] + bi0)) * d1);
                o1.y = tf32f((tanhf(u1.y + bu1) - sigmoidf(acc[mi][ni][3] + bi1)) * d1);
            } else {
                float b0 = bias[col], b1v = bias[col + 1];
                o0.x = sigmoidf(acc[mi][ni][0] + b0);
                o0.y = sigmoidf(acc[mi][ni][1] + b1v);
                o1.x = sigmoidf(acc[mi][ni][2] + b0);
                o1.y = sigmoidf(acc[mi][ni][3] + b1v);
            }
            *(float2*)(OUT + (size_t)r0 * ldout + col)       = o0;
            *(float2*)(OUT + (size_t)(r0 + 8) * ldout + col) = o1;
        }
    }
}

// ---------------- K4: final GEMV + sigmoid ----------------
__global__ void k_out(const float* __restrict__ W2, const float* __restrict__ b2,
                      float* __restrict__ out)
{
    int gw   = (blockIdx.x * blockDim.x + threadIdx.x) >> 5;
    int lane = threadIdx.x & 31;
    if (gw >= BATCH) return;
    const float4* h4 = (const float4*)(g_H + (size_t)gw * H2);
    const float4* w4 = (const float4*)W2;
    float s = 0.f;
    #pragma unroll
    for (int i = 0; i < 2; i++) {
        float4 hv = h4[lane + i * 32], wv = w4[lane + i * 32];
        s += hv.x * wv.x + hv.y * wv.y + hv.z * wv.z + hv.w * wv.w;
    }
    #pragma unroll
    for (int o = 16; o; o >>= 1) s += __shfl_xor_sync(0xffffffffu, s, o);
    if (lane == 0) out[gw] = sigmoidf(s + b2[0]);
}

// ---------------- host: numpy-legacy MT19937 graph reconstruction ----------------
namespace {
struct MT { uint32_t mt[624]; int idx; };
static void mt_seed(MT& s, uint32_t seed) {
    s.mt[0] = seed;
    for (int i = 1; i < 624; i++)
        s.mt[i] = 1812433253u * (s.mt[i-1] ^ (s.mt[i-1] >> 30)) + (uint32_t)i;
    s.idx = 624;
}
static uint32_t mt_next(MT& s) {
    if (s.idx >= 624) {
        for (int i = 0; i < 624; i++) {
            uint32_t y = (s.mt[i] & 0x80000000u) | (s.mt[(i+1) % 624] & 0x7fffffffu);
            s.mt[i] = s.mt[(i+397) % 624] ^ (y >> 1) ^ ((y & 1u) ? 0x9908b0dfu : 0u);
        }
        s.idx = 0;
    }
    uint32_t y = s.mt[s.idx++];
    y ^= y >> 11;
    y ^= (y << 7)  & 0x9d2c5680u;
    y ^= (y << 15) & 0xefc60000u;
    y ^= y >> 18;
    return y;
}
static uint32_t draw_bounded(MT& s, uint32_t rng) {
    uint32_t mask = rng; mask |= mask >> 1; mask |= mask >> 2; mask |= mask >> 4;
    mask |= mask >> 8; mask |= mask >> 16;
    uint32_t v;
    do { v = mt_next(s) & mask; } while (v > rng);
    return v;
}
static void build_graph(Sched& sc, int& E) {
    MT mt; mt_seed(mt, 0u);
    int off = 0;
    int level[NC];
    for (int k = 0; k < NC; k++) {
        int l = 0;
        if (k > 0) {
            int hi = (k < 3 ? k : 3) + 1;
            l = (int)draw_bounded(mt, (uint32_t)(hi - 1));
        }
        int preds[3] = {0, 0, 0};
        if (l > 0) {
            int arr[NC];
            for (int i = 0; i < k; i++) arr[i] = i;
            for (int i = k - 1; i >= 1; i--) {
                uint32_t j = draw_bounded(mt, (uint32_t)i);
                int tmp = arr[i]; arr[i] = arr[(int)j]; arr[(int)j] = tmp;
            }
            for (int jj = 0; jj < l; jj++) preds[jj] = arr[jj];
            for (int a = 0; a < l; a++)
                for (int b2_ = a + 1; b2_ < l; b2_++)
                    if (preds[b2_] < preds[a]) { int tm = preds[a]; preds[a] = preds[b2_]; preds[b2_] = tm; }
        }
        sc.lp[k] = (unsigned char)l;
        sc.off[k] = (unsigned short)off;
        sc.invl[k] = (l > 0) ? 1.0f / (float)l : 1.0f;
        for (int jj = 0; jj < 3; jj++) sc.pred[k][jj] = (unsigned char)(jj < l ? preds[jj] : 0);
        int lvl = 0;
        for (int jj = 0; jj < l; jj++) {
            int pl = level[preds[jj]] + 1;
            if (pl > lvl) lvl = pl;
        }
        level[k] = lvl;
        off += l;
    }
    E = off;
    // bucket concepts by level
    int maxlvl = 0;
    for (int k = 0; k < NC; k++) if (level[k] > maxlvl) maxlvl = level[k];
    sc.nLvl = maxlvl + 1;
    int pos = 0;
    for (int lv = 0; lv <= maxlvl; lv++) {
        sc.lvlStart[lv] = (short)pos;
        for (int k = 0; k < NC; k++)
            if (level[k] == lv) sc.order[pos++] = (unsigned char)k;
    }
    sc.lvlStart[maxlvl + 1] = (short)pos;
}
} // namespace

extern "C" void kernel_launch(void* const* d_in, const int* in_sizes, int n_in,
                              void* d_out, int out_size)
{
    Sched sc; int E;
    build_graph(sc, E);

    const int*   uid    = (const int*)  d_in[0];
    const int*   qid    = (const int*)  d_in[1];
    const float* priori = (const float*)d_in[2];
    const float* cpd    = (const float*)d_in[3];
    const float* cnd    = (const float*)d_in[4];
    const float* idiff  = (const float*)d_in[5];
    const float* idisc  = (const float*)d_in[6];
    const float* qt     = (const float*)d_in[7];
    const float* bu     = (const float*)d_in[9];
    const float* bi     = (const float*)d_in[11];
    const float* b1     = (const float*)d_in[13];
    const float* W2     = (const float*)d_in[14];
    const float* b2     = (const float*)d_in[15];
    float* out = (float*)d_out;

    int Ein = in_sizes[3] / NUM_USER;
    if (Ein > 0 && Ein <= MAXE) E = Ein;

    static bool attr_done = false;
    if (!attr_done) {
        cudaFuncSetAttribute(gemm_cp<128, 0>, cudaFuncAttributeMaxDynamicSharedMemorySize, SMEM_GEMM);
        cudaFuncSetAttribute(gemm_cp<128, 1>, cudaFuncAttributeMaxDynamicSharedMemorySize, SMEM_GEMM);
        cudaFuncSetAttribute(gemm_cp<512, 2>, cudaFuncAttributeMaxDynamicSharedMemorySize, SMEM_GEMM);
        attr_done = true;
    }

    k_prep<<<(H2 * DH + 255) / 256, 256>>>((const float*)d_in[8], (const float*)d_in[10],
                                           (const float*)d_in[12]);

    k_elem2<<<(BATCH * NC + 255) / 256, 256>>>(qid, idiff, idisc, qt);

    k_mastery2<<<BATCH / WPB, WPB * 32>>>(uid, qid, priori, cpd, cnd, qt, sc, E);

    gemm_cp<128, 0><<<dim3(BATCH / 128, DH / 128), 256, SMEM_GEMM>>>(nullptr, nullptr);
    gemm_cp<128, 1><<<dim3(BATCH / 128, DH / 128), 256, SMEM_GEMM>>>(bu, bi);
    gemm_cp<512, 2><<<dim3(BATCH / 128, H2 / 128), 256, SMEM_GEMM>>>(b1, nullptr);

    k_out<<<(BATCH * 32 + 255) / 256, 256>>>(W2, b2, out);
}

// round 8
// speedup vs baseline: 1.7603x; 1.1029x over previous
#include <cuda_runtime.h>
#include <cstdint>

#define NUM_USER     200000
#define NUM_QUESTION 20000
#define NC           128
#define DH           512
#define H2           256
#define BATCH        16384
#define MAXE         384
#define LDS_         36                  // smem row stride (floats)
#define TILEF        (128 * LDS_)        // floats per 128-row tile

// k_factor: stage = A(128) + Bm(128) + Wu(64) + Wi(64) = 384 rows
#define F_ROWS       384
#define F_STAGEF     (F_ROWS * LDS_)     // 13824 floats
#define SMEM_FACTOR  (2 * F_STAGEF * 4)  // 110592 B (2 stages)

// k_mlp: stage = A(128) + W(128) = 256 rows, 3 stages
#define M_STAGEF     (2 * TILEF)         // 9216 floats
#define SMEM_MLP     (3 * M_STAGEF * 4)  // 110592 B

// ---------------- scratch (__device__ globals) ----------------
__device__ float g_Bm [BATCH * NC];
__device__ float g_Disc[BATCH];
__device__ float g_A  [BATCH * NC];
__device__ float g_X  [BATCH * DH];
__device__ float g_H  [BATCH * H2];
__device__ float g_Wu [DH * NC];
__device__ float g_Wi [DH * NC];
__device__ float g_W1 [H2 * DH];

struct Sched {
    unsigned char  order[NC];
    unsigned char  lp[NC];
    unsigned short off[NC];
    unsigned char  pred[NC][3];
    float          invl[NC];
    short          lvlStart[NC + 1];
    int            nLvl;
};

__device__ __forceinline__ float sigmoidf(float x) {
    return __fdividef(1.0f, 1.0f + __expf(-x));
}
__device__ __forceinline__ float tf32f(float x) {
    uint32_t r;
    asm("cvt.rna.tf32.f32 %0, %1;" : "=r"(r) : "f"(x));
    return __uint_as_float(r);
}
__device__ __forceinline__ uint32_t smem_u32(const void* p) {
    uint32_t a;
    asm("{ .reg .u64 t; cvta.to.shared.u64 t, %1; cvt.u32.u64 %0, t; }" : "=r"(a) : "l"(p));
    return a;
}
__device__ __forceinline__ void cp16(uint32_t s, const void* g) {
    asm volatile("cp.async.cg.shared.global [%0], [%1], 16;" :: "r"(s), "l"(g));
}
__device__ __forceinline__ void cp_commit() {
    asm volatile("cp.async.commit_group;" ::: "memory");
}
__device__ __forceinline__ void cp_wait0() {
    asm volatile("cp.async.wait_group 0;" ::: "memory");
}
__device__ __forceinline__ void cp_wait1() {
    asm volatile("cp.async.wait_group 1;" ::: "memory");
}
__device__ __forceinline__ void mma_tf32(float c[4],
                                         uint32_t a0, uint32_t a1, uint32_t a2, uint32_t a3,
                                         uint32_t b0, uint32_t b1) {
    asm volatile(
        "mma.sync.aligned.m16n8k8.row.col.f32.tf32.tf32.f32 "
        "{%0,%1,%2,%3}, {%4,%5,%6,%7}, {%8,%9}, {%0,%1,%2,%3};"
        : "+f"(c[0]), "+f"(c[1]), "+f"(c[2]), "+f"(c[3])
        : "r"(a0), "r"(a1), "r"(a2), "r"(a3), "r"(b0), "r"(b1));
}

// ---------------- K-1: pre-round weights to tf32 ----------------
__global__ void k_prep(const float* __restrict__ Wu, const float* __restrict__ Wi,
                       const float* __restrict__ W1)
{
    int i = blockIdx.x * blockDim.x + threadIdx.x;
    if (i < DH * NC) {
        g_Wu[i] = tf32f(Wu[i]);
        g_Wi[i] = tf32f(Wi[i]);
    }
    if (i < H2 * DH) g_W1[i] = tf32f(W1[i]);
}

// ---------------- K0: Bm / disc ----------------
__global__ void k_elem2(const int* __restrict__ qid,
                        const float* __restrict__ idiff, const float* __restrict__ idisc,
                        const float* __restrict__ qt)
{
    int idx = blockIdx.x * blockDim.x + threadIdx.x;
    if (idx >= BATCH * NC) return;
    int b = idx >> 7, k = idx & 127;
    int q = qid[b];
    g_Bm[idx] = tf32f(sigmoidf(idiff[(size_t)q * NC + k]) * qt[(size_t)q * NC + k]);
    if (k == 0) g_Disc[b] = sigmoidf(idisc[q]);
}

// ---------------- K1: fused warp-per-row level-parallel posterior ----------------
#define WPB 8
__global__ void __launch_bounds__(WPB * 32) k_mastery2(
    const int* __restrict__ uid, const int* __restrict__ qid,
    const float* __restrict__ priori,
    const float* __restrict__ condi_p, const float* __restrict__ condi_n,
    const float* __restrict__ qt, Sched s, int E)
{
    __shared__ float sm_m [WPB][NC];
    __shared__ float sm_cp[WPB][MAXE];
    __shared__ float sm_cn[WPB][MAXE];

    int lane = threadIdx.x & 31, w = threadIdx.x >> 5;
    int b = blockIdx.x * WPB + w;
    int u = uid[b];

    const float* cpr = condi_p + (size_t)u * E;
    const float* cnr = condi_n + (size_t)u * E;
    for (int j = lane; j < E; j += 32) {
        sm_cp[w][j] = sigmoidf(cpr[j]);
        sm_cn[w][j] = sigmoidf(cnr[j]);
    }
    __syncwarp();

    const float* pr = priori + (size_t)u * NC;
    for (int lv = 0; lv < s.nLvl; lv++) {
        int e = s.lvlStart[lv + 1];
        for (int i = s.lvlStart[lv] + lane; i < e; i += 32) {
            int k = s.order[i];
            int l = s.lp[k];
            float v;
            if (l == 0) {
                v = sigmoidf(pr[k]);
            } else {
                int o = s.off[k];
                float inv = s.invl[k];
                v = 1.0f;
                #pragma unroll 1
                for (int j = 0; j < l; j++) {
                    float mp = sm_m[w][s.pred[k][j]];
                    float a = sm_cp[w][o + j], bb = sm_cn[w][o + j];
                    if (l > 1) { a = __powf(a, inv); bb = __powf(bb, inv); }
                    v *= a * mp + bb * (1.0f - mp);
                }
            }
            sm_m[w][k] = v;
        }
        __syncwarp();
    }

    int q = qid[b];
    const float* qr = qt + (size_t)q * NC;
    float* ao = g_A + (size_t)b * NC;
    for (int k = lane; k < NC; k += 32)
        ao[k] = tf32f(sm_m[w][k] * qr[k]);
}

// ---------------- K2: fused dual GEMM -> X  (CTA 128M x 64N, BK=32) ----------------
// X = (tanh(A@Wu^T + bu) - sigmoid(Bm@Wi^T + bi)) * disc
// 8 warps: 2M x 4N, warp tile 64x16; dual acc 32+32 floats.
// smem stage rows: [0,128)=A  [128,256)=Bm  [256,320)=Wu  [320,384)=Wi
__global__ void __launch_bounds__(256, 2) k_factor(const float* __restrict__ bu,
                                                   const float* __restrict__ bi)
{
    extern __shared__ uint32_t smx[];
    int t = threadIdx.x, lane = t & 31, warp = t >> 5;
    int wm = (warp & 1) * 64;
    int wn = (warp >> 1) * 16;
    int m0 = blockIdx.x * 128, n0 = blockIdx.y * 64;
    int g   = lane >> 2;
    int tig = lane & 3;

    const float* Ab  = g_A  + (size_t)m0 * NC;
    const float* Bmb = g_Bm + (size_t)m0 * NC;
    const float* Wub = g_Wu + (size_t)n0 * NC;
    const float* Wib = g_Wi + (size_t)n0 * NC;

    int cr = t >> 3;             // 0..31
    int cc = (t & 7) * 4;        // 0..28

    float cU[4][2][4], cI[4][2][4];
    #pragma unroll
    for (int mi = 0; mi < 4; mi++)
        #pragma unroll
        for (int ni = 0; ni < 2; ni++)
            #pragma unroll
            for (int q = 0; q < 4; q++) { cU[mi][ni][q] = 0.f; cI[mi][ni][q] = 0.f; }

    const int NCH = NC / 32;     // 4

    auto issue = [&](int ch, uint32_t* st) {
        uint32_t sb = smem_u32(st);
        int kc = ch * 32;
        #pragma unroll
        for (int i = 0; i < 12; i++) {
            int r = cr + i * 32;
            const float* src;
            if      (i < 4)  src = Ab  + (size_t)r * NC;
            else if (i < 8)  src = Bmb + (size_t)(r - 128) * NC;
            else if (i < 10) src = Wub + (size_t)(r - 256) * NC;
            else             src = Wib + (size_t)(r - 320) * NC;
            cp16(sb + (uint32_t)(r * LDS_ + cc) * 4, src + kc + cc);
        }
    };

    issue(0, smx);
    cp_commit();

    #pragma unroll
    for (int ch = 0; ch < NCH; ch++) {
        cp_wait0();
        __syncthreads();
        if (ch + 1 < NCH) {
            issue(ch + 1, smx + ((ch + 1) & 1) * F_STAGEF);
            cp_commit();
        }
        uint32_t* st  = smx + (ch & 1) * F_STAGEF;
        uint32_t* sA  = st;
        uint32_t* sBm = st + 128 * LDS_;
        uint32_t* sWu = st + 256 * LDS_;
        uint32_t* sWi = st + 320 * LDS_;
        #pragma unroll
        for (int kk = 0; kk < 4; kk++) {
            int kb = kk * 8;
            uint32_t bfu[2][2], bfi[2][2];
            #pragma unroll
            for (int ni = 0; ni < 2; ni++) {
                int n = wn + ni * 8 + g;
                bfu[ni][0] = sWu[n * LDS_ + kb + tig];
                bfu[ni][1] = sWu[n * LDS_ + kb + tig + 4];
                bfi[ni][0] = sWi[n * LDS_ + kb + tig];
                bfi[ni][1] = sWi[n * LDS_ + kb + tig + 4];
            }
            #pragma unroll
            for (int mi = 0; mi < 4; mi++) {
                int r = wm + mi * 16 + g;
                uint32_t aA0 = sA [r * LDS_ + kb + tig];
                uint32_t aA1 = sA [(r + 8) * LDS_ + kb + tig];
                uint32_t aA2 = sA [r * LDS_ + kb + tig + 4];
                uint32_t aA3 = sA [(r + 8) * LDS_ + kb + tig + 4];
                uint32_t aB0 = sBm[r * LDS_ + kb + tig];
                uint32_t aB1 = sBm[(r + 8) * LDS_ + kb + tig];
                uint32_t aB2 = sBm[r * LDS_ + kb + tig + 4];
                uint32_t aB3 = sBm[(r + 8) * LDS_ + kb + tig + 4];
                #pragma unroll
                for (int ni = 0; ni < 2; ni++) {
                    mma_tf32(cU[mi][ni], aA0, aA1, aA2, aA3, bfu[ni][0], bfu[ni][1]);
                    mma_tf32(cI[mi][ni], aB0, aB1, aB2, aB3, bfi[ni][0], bfi[ni][1]);
                }
            }
        }
        __syncthreads();
    }

    // fused combine epilogue
    #pragma unroll
    for (int mi = 0; mi < 4; mi++) {
        int r0 = m0 + wm + mi * 16 + g;
        float d0 = g_Disc[r0], d1 = g_Disc[r0 + 8];
        #pragma unroll
        for (int ni = 0; ni < 2; ni++) {
            int col = n0 + wn + ni * 8 + tig * 2;
            float bu0 = bu[col], bu1 = bu[col + 1];
            float bi0 = bi[col], bi1 = bi[col + 1];
            float2 o0, o1;
            o0.x = tf32f((tanhf(cU[mi][ni][0] + bu0) - sigmoidf(cI[mi][ni][0] + bi0)) * d0);
            o0.y = tf32f((tanhf(cU[mi][ni][1] + bu1) - sigmoidf(cI[mi][ni][1] + bi1)) * d0);
            o1.x = tf32f((tanhf(cU[mi][ni][2] + bu0) - sigmoidf(cI[mi][ni][2] + bi0)) * d1);
            o1.y = tf32f((tanhf(cU[mi][ni][3] + bu1) - sigmoidf(cI[mi][ni][3] + bi1)) * d1);
            *(float2*)(g_X + (size_t)r0 * DH + col)       = o0;
            *(float2*)(g_X + (size_t)(r0 + 8) * DH + col) = o1;
        }
    }
}

// ---------------- K3: 3-stage pipelined GEMM, H = sigmoid(X@W1^T + b1) ----------------
__global__ void __launch_bounds__(256, 2) k_mlp(const float* __restrict__ bias)
{
    extern __shared__ uint32_t smx[];
    int t = threadIdx.x, lane = t & 31, warp = t >> 5;
    int wm = (warp & 1) * 64;
    int wn = (warp >> 1) * 32;
    int m0 = blockIdx.x * 128, n0 = blockIdx.y * 128;
    int g   = lane >> 2;
    int tig = lane & 3;

    const float* Ab = g_X  + (size_t)m0 * DH;
    const float* Wb = g_W1 + (size_t)n0 * DH;

    int cr = t >> 3;
    int cc = (t & 7) * 4;

    float acc[4][4][4];
    #pragma unroll
    for (int mi = 0; mi < 4; mi++)
        #pragma unroll
        for (int ni = 0; ni < 4; ni++)
            #pragma unroll
            for (int q = 0; q < 4; q++) acc[mi][ni][q] = 0.f;

    const int NCH = DH / 32;   // 16

    auto issue = [&](int ch, uint32_t* st) {
        uint32_t sA = smem_u32(st), sW = smem_u32(st + TILEF);
        int kc = ch * 32;
        #pragma unroll
        for (int i = 0; i < 4; i++) {
            int r = cr + i * 32;
            cp16(sA + (uint32_t)(r * LDS_ + cc) * 4, Ab + (size_t)r * DH + kc + cc);
            cp16(sW + (uint32_t)(r * LDS_ + cc) * 4, Wb + (size_t)r * DH + kc + cc);
        }
    };

    issue(0, smx);             cp_commit();
    issue(1, smx + M_STAGEF);  cp_commit();

    #pragma unroll 4
    for (int ch = 0; ch < NCH; ch++) {
        cp_wait1();            // stage ch ready (<=1 group pending)
        __syncthreads();
        if (ch + 2 < NCH) {
            int s2 = (ch + 2) % 3;
            issue(ch + 2, smx + s2 * M_STAGEF);
        }
        cp_commit();           // uniform commit keeps group accounting exact
        uint32_t* sA = smx + (ch % 3) * M_STAGEF;
        uint32_t* sW = sA + TILEF;
        #pragma unroll
        for (int kk = 0; kk < 4; kk++) {
            int kb = kk * 8;
            uint32_t bf[4][2];
            #pragma unroll
            for (int ni = 0; ni < 4; ni++) {
                int n = wn + ni * 8 + g;
                bf[ni][0] = sW[n * LDS_ + kb + tig];
                bf[ni][1] = sW[n * LDS_ + kb + tig + 4];
            }
            #pragma unroll
            for (int mi = 0; mi < 4; mi++) {
                int r = wm + mi * 16 + g;
                uint32_t a0 = sA[r * LDS_ + kb + tig];
                uint32_t a1 = sA[(r + 8) * LDS_ + kb + tig];
                uint32_t a2 = sA[r * LDS_ + kb + tig + 4];
                uint32_t a3 = sA[(r + 8) * LDS_ + kb + tig + 4];
                #pragma unroll
                for (int ni = 0; ni < 4; ni++)
                    mma_tf32(acc[mi][ni], a0, a1, a2, a3, bf[ni][0], bf[ni][1]);
            }
        }
        __syncthreads();
    }

    #pragma unroll
    for (int mi = 0; mi < 4; mi++) {
        int r0 = m0 + wm + mi * 16 + g;
        #pragma unroll
        for (int ni = 0; ni < 4; ni++) {
            int col = n0 + wn + ni * 8 + tig * 2;
            float b0 = bias[col], b1v = bias[col + 1];
            float2 o0, o1;
            o0.x = sigmoidf(acc[mi][ni][0] + b0);
            o0.y = sigmoidf(acc[mi][ni][1] + b1v);
            o1.x = sigmoidf(acc[mi][ni][2] + b0);
            o1.y = sigmoidf(acc[mi][ni][3] + b1v);
            *(float2*)(g_H + (size_t)r0 * H2 + col)       = o0;
            *(float2*)(g_H + (size_t)(r0 + 8) * H2 + col) = o1;
        }
    }
}

// ---------------- K4: final GEMV + sigmoid ----------------
__global__ void k_out(const float* __restrict__ W2, const float* __restrict__ b2,
                      float* __restrict__ out)
{
    int gw   = (blockIdx.x * blockDim.x + threadIdx.x) >> 5;
    int lane = threadIdx.x & 31;
    if (gw >= BATCH) return;
    const float4* h4 = (const float4*)(g_H + (size_t)gw * H2);
    const float4* w4 = (const float4*)W2;
    float s = 0.f;
    #pragma unroll
    for (int i = 0; i < 2; i++) {
        float4 hv = h4[lane + i * 32], wv = w4[lane + i * 32];
        s += hv.x * wv.x + hv.y * wv.y + hv.z * wv.z + hv.w * wv.w;
    }
    #pragma unroll
    for (int o = 16; o; o >>= 1) s += __shfl_xor_sync(0xffffffffu, s, o);
    if (lane == 0) out[gw] = sigmoidf(s + b2[0]);
}

// ---------------- host: numpy-legacy MT19937 graph reconstruction ----------------
namespace {
struct MT { uint32_t mt[624]; int idx; };
static void mt_seed(MT& s, uint32_t seed) {
    s.mt[0] = seed;
    for (int i = 1; i < 624; i++)
        s.mt[i] = 1812433253u * (s.mt[i-1] ^ (s.mt[i-1] >> 30)) + (uint32_t)i;
    s.idx = 624;
}
static uint32_t mt_next(MT& s) {
    if (s.idx >= 624) {
        for (int i = 0; i < 624; i++) {
            uint32_t y = (s.mt[i] & 0x80000000u) | (s.mt[(i+1) % 624] & 0x7fffffffu);
            s.mt[i] = s.mt[(i+397) % 624] ^ (y >> 1) ^ ((y & 1u) ? 0x9908b0dfu : 0u);
        }
        s.idx = 0;
    }
    uint32_t y = s.mt[s.idx++];
    y ^= y >> 11;
    y ^= (y << 7)  & 0x9d2c5680u;
    y ^= (y << 15) & 0xefc60000u;
    y ^= y >> 18;
    return y;
}
static uint32_t draw_bounded(MT& s, uint32_t rng) {
    uint32_t mask = rng; mask |= mask >> 1; mask |= mask >> 2; mask |= mask >> 4;
    mask |= mask >> 8; mask |= mask >> 16;
    uint32_t v;
    do { v = mt_next(s) & mask; } while (v > rng);
    return v;
}
static void build_graph(Sched& sc, int& E) {
    MT mt; mt_seed(mt, 0u);
    int off = 0;
    int level[NC];
    for (int k = 0; k < NC; k++) {
        int l = 0;
        if (k > 0) {
            int hi = (k < 3 ? k : 3) + 1;
            l = (int)draw_bounded(mt, (uint32_t)(hi - 1));
        }
        int preds[3] = {0, 0, 0};
        if (l > 0) {
            int arr[NC];
            for (int i = 0; i < k; i++) arr[i] = i;
            for (int i = k - 1; i >= 1; i--) {
                uint32_t j = draw_bounded(mt, (uint32_t)i);
                int tmp = arr[i]; arr[i] = arr[(int)j]; arr[(int)j] = tmp;
            }
            for (int jj = 0; jj < l; jj++) preds[jj] = arr[jj];
            for (int a = 0; a < l; a++)
                for (int b2_ = a + 1; b2_ < l; b2_++)
                    if (preds[b2_] < preds[a]) { int tm = preds[a]; preds[a] = preds[b2_]; preds[b2_] = tm; }
        }
        sc.lp[k] = (unsigned char)l;
        sc.off[k] = (unsigned short)off;
        sc.invl[k] = (l > 0) ? 1.0f / (float)l : 1.0f;
        for (int jj = 0; jj < 3; jj++) sc.pred[k][jj] = (unsigned char)(jj < l ? preds[jj] : 0);
        int lvl = 0;
        for (int jj = 0; jj < l; jj++) {
            int pl = level[preds[jj]] + 1;
            if (pl > lvl) lvl = pl;
        }
        level[k] = lvl;
        off += l;
    }
    E = off;
    int maxlvl = 0;
    for (int k = 0; k < NC; k++) if (level[k] > maxlvl) maxlvl = level[k];
    sc.nLvl = maxlvl + 1;
    int pos = 0;
    for (int lv = 0; lv <= maxlvl; lv++) {
        sc.lvlStart[lv] = (short)pos;
        for (int k = 0; k < NC; k++)
            if (level[k] == lv) sc.order[pos++] = (unsigned char)k;
    }
    sc.lvlStart[maxlvl + 1] = (short)pos;
}
} // namespace

extern "C" void kernel_launch(void* const* d_in, const int* in_sizes, int n_in,
                              void* d_out, int out_size)
{
    Sched sc; int E;
    build_graph(sc, E);

    const int*   uid    = (const int*)  d_in[0];
    const int*   qid    = (const int*)  d_in[1];
    const float* priori = (const float*)d_in[2];
    const float* cpd    = (const float*)d_in[3];
    const float* cnd    = (const float*)d_in[4];
    const float* idiff  = (const float*)d_in[5];
    const float* idisc  = (const float*)d_in[6];
    const float* qt     = (const float*)d_in[7];
    const float* bu     = (const float*)d_in[9];
    const float* bi     = (const float*)d_in[11];
    const float* b1     = (const float*)d_in[13];
    const float* W2     = (const float*)d_in[14];
    const float* b2     = (const float*)d_in[15];
    float* out = (float*)d_out;

    int Ein = in_sizes[3] / NUM_USER;
    if (Ein > 0 && Ein <= MAXE) E = Ein;

    static bool attr_done = false;
    if (!attr_done) {
        cudaFuncSetAttribute(k_factor, cudaFuncAttributeMaxDynamicSharedMemorySize, SMEM_FACTOR);
        cudaFuncSetAttribute(k_mlp,    cudaFuncAttributeMaxDynamicSharedMemorySize, SMEM_MLP);
        attr_done = true;
    }

    k_prep<<<(H2 * DH + 255) / 256, 256>>>((const float*)d_in[8], (const float*)d_in[10],
                                           (const float*)d_in[12]);

    k_elem2<<<(BATCH * NC + 255) / 256, 256>>>(qid, idiff, idisc, qt);

    k_mastery2<<<BATCH / WPB, WPB * 32>>>(uid, qid, priori, cpd, cnd, qt, sc, E);

    k_factor<<<dim3(BATCH / 128, DH / 64), 256, SMEM_FACTOR>>>(bu, bi);

    k_mlp<<<dim3(BATCH / 128, H2 / 128), 256, SMEM_MLP>>>(b1);

    k_out<<<(BATCH * 32 + 255) / 256, 256>>>(W2, b2, out);
}

// round 9
// speedup vs baseline: 2.1340x; 1.2123x over previous
#include <cuda_runtime.h>
#include <cuda_bf16.h>
#include <cstdint>

#define NUM_USER     200000
#define NUM_QUESTION 20000
#define NC           128
#define DH           512
#define H2           256
#define BATCH        16384
#define MAXE         384
#define KW           (NC / 2)     // 64 u32 per bf16x2 row (K=128)
#define DHW          (DH / 2)     // 256 u32 per row (K=512)
#define LDS2         20           // smem row stride in u32 (16 data + 4 pad)

// factor stage: A(128)+Bm(128)+Wu(64)+Wi(64) = 384 rows x 20 u32
#define F_STAGEU     (384 * LDS2)
#define SMEM_FACTOR  (2 * F_STAGEU * 4)   // 61440 B
// mlp stage: A(128)+W(128) = 256 rows x 20 u32, 3 stages
#define M_STAGEU     (256 * LDS2)
#define SMEM_MLP     (3 * M_STAGEU * 4)   // 61440 B

// ---------------- scratch (__device__ globals) ----------------
__device__ uint32_t g_Bm2[BATCH * KW];     // bf16x2 packed
__device__ float    g_Disc[BATCH];
__device__ uint32_t g_A2 [BATCH * KW];     // bf16x2 packed
__device__ uint32_t g_X2 [BATCH * DHW];    // bf16x2 packed
__device__ float    g_H  [BATCH * H2];
__device__ uint32_t g_Wu2[DH * KW];
__device__ uint32_t g_Wi2[DH * KW];
__device__ uint32_t g_W12[H2 * DHW];

struct Sched {
    unsigned char  order[NC];
    unsigned char  lp[NC];
    unsigned short off[NC];
    unsigned char  pred[NC][3];
    float          invl[NC];
    short          lvlStart[NC + 1];
    int            nLvl;
};

__device__ __forceinline__ float sigmoidf(float x) {
    return __fdividef(1.0f, 1.0f + __expf(-x));
}
__device__ __forceinline__ uint32_t packbf(float x, float y) {
    __nv_bfloat162 v = __floats2bfloat162_rn(x, y);
    return *(uint32_t*)&v;
}
__device__ __forceinline__ uint32_t smem_u32(const void* p) {
    uint32_t a;
    asm("{ .reg .u64 t; cvta.to.shared.u64 t, %1; cvt.u32.u64 %0, t; }" : "=r"(a) : "l"(p));
    return a;
}
__device__ __forceinline__ void cp16(uint32_t s, const void* g) {
    asm volatile("cp.async.cg.shared.global [%0], [%1], 16;" :: "r"(s), "l"(g));
}
__device__ __forceinline__ void cp_commit() {
    asm volatile("cp.async.commit_group;" ::: "memory");
}
__device__ __forceinline__ void cp_wait0() {
    asm volatile("cp.async.wait_group 0;" ::: "memory");
}
__device__ __forceinline__ void cp_wait1() {
    asm volatile("cp.async.wait_group 1;" ::: "memory");
}
// bf16 MMA: D(16x8,f32) += A(16x16,bf16) * B(8x16,bf16)^T
__device__ __forceinline__ void mma_bf16(float c[4],
                                         uint32_t a0, uint32_t a1, uint32_t a2, uint32_t a3,
                                         uint32_t b0, uint32_t b1) {
    asm volatile(
        "mma.sync.aligned.m16n8k16.row.col.f32.bf16.bf16.f32 "
        "{%0,%1,%2,%3}, {%4,%5,%6,%7}, {%8,%9}, {%0,%1,%2,%3};"
        : "+f"(c[0]), "+f"(c[1]), "+f"(c[2]), "+f"(c[3])
        : "r"(a0), "r"(a1), "r"(a2), "r"(a3), "r"(b0), "r"(b1));
}

// ---------------- K-1: pack weights to bf16x2 ----------------
__global__ void k_prep(const float* __restrict__ Wu, const float* __restrict__ Wi,
                       const float* __restrict__ W1)
{
    int i = blockIdx.x * blockDim.x + threadIdx.x;
    if (i < DH * KW) {
        g_Wu2[i] = packbf(Wu[2 * i], Wu[2 * i + 1]);
        g_Wi2[i] = packbf(Wi[2 * i], Wi[2 * i + 1]);
    }
    if (i < H2 * DHW)
        g_W12[i] = packbf(W1[2 * i], W1[2 * i + 1]);
}

// ---------------- K0: Bm / disc ----------------
__global__ void k_elem2(const int* __restrict__ qid,
                        const float* __restrict__ idiff, const float* __restrict__ idisc,
                        const float* __restrict__ qt)
{
    int idx = blockIdx.x * blockDim.x + threadIdx.x;
    if (idx >= BATCH * KW) return;
    int b = idx >> 6, j = idx & 63;
    int q = qid[b];
    size_t base = (size_t)q * NC + 2 * j;
    float v0 = sigmoidf(idiff[base])     * qt[base];
    float v1 = sigmoidf(idiff[base + 1]) * qt[base + 1];
    g_Bm2[idx] = packbf(v0, v1);
    if (j == 0) g_Disc[b] = sigmoidf(idisc[q]);
}

// ---------------- K1: fused warp-per-row level-parallel posterior ----------------
#define WPB 8
__global__ void __launch_bounds__(WPB * 32) k_mastery2(
    const int* __restrict__ uid, const int* __restrict__ qid,
    const float* __restrict__ priori,
    const float* __restrict__ condi_p, const float* __restrict__ condi_n,
    const float* __restrict__ qt, Sched s, int E)
{
    __shared__ float sm_m [WPB][NC];
    __shared__ float sm_cp[WPB][MAXE];
    __shared__ float sm_cn[WPB][MAXE];

    int lane = threadIdx.x & 31, w = threadIdx.x >> 5;
    int b = blockIdx.x * WPB + w;
    int u = uid[b];

    const float* cpr = condi_p + (size_t)u * E;
    const float* cnr = condi_n + (size_t)u * E;
    for (int j = lane; j < E; j += 32) {
        sm_cp[w][j] = sigmoidf(cpr[j]);
        sm_cn[w][j] = sigmoidf(cnr[j]);
    }
    __syncwarp();

    const float* pr = priori + (size_t)u * NC;
    for (int lv = 0; lv < s.nLvl; lv++) {
        int e = s.lvlStart[lv + 1];
        for (int i = s.lvlStart[lv] + lane; i < e; i += 32) {
            int k = s.order[i];
            int l = s.lp[k];
            float v;
            if (l == 0) {
                v = sigmoidf(pr[k]);
            } else {
                int o = s.off[k];
                float inv = s.invl[k];
                v = 1.0f;
                #pragma unroll 1
                for (int j = 0; j < l; j++) {
                    float mp = sm_m[w][s.pred[k][j]];
                    float a = sm_cp[w][o + j], bb = sm_cn[w][o + j];
                    if (l > 1) { a = __powf(a, inv); bb = __powf(bb, inv); }
                    v *= a * mp + bb * (1.0f - mp);
                }
            }
            sm_m[w][k] = v;
        }
        __syncwarp();
    }

    int q = qid[b];
    const float* qr = qt + (size_t)q * NC;
    uint32_t* ao = g_A2 + (size_t)b * KW;
    for (int j = lane; j < KW; j += 32)
        ao[j] = packbf(sm_m[w][2 * j] * qr[2 * j], sm_m[w][2 * j + 1] * qr[2 * j + 1]);
}

// ---------------- K2: fused dual bf16 GEMM -> X  (CTA 128M x 64N, BK=32) ----------------
// X = (tanh(A@Wu^T + bu) - sigmoid(Bm@Wi^T + bi)) * disc   -> stored bf16x2
__global__ void __launch_bounds__(256, 2) k_factor(const float* __restrict__ bu,
                                                   const float* __restrict__ bi)
{
    extern __shared__ uint32_t smx[];
    int t = threadIdx.x, lane = t & 31, warp = t >> 5;
    int wm = (warp & 1) * 64;
    int wn = (warp >> 1) * 16;
    int m0 = blockIdx.x * 128, n0 = blockIdx.y * 64;
    int g   = lane >> 2;
    int tig = lane & 3;

    const uint32_t* Ab  = g_A2  + (size_t)m0 * KW;
    const uint32_t* Bmb = g_Bm2 + (size_t)m0 * KW;
    const uint32_t* Wub = g_Wu2 + (size_t)n0 * KW;
    const uint32_t* Wib = g_Wi2 + (size_t)n0 * KW;

    int cr = t >> 2;             // 0..63
    int cc = (t & 3) * 4;        // u32 col: 0,4,8,12

    float cU[4][2][4], cI[4][2][4];
    #pragma unroll
    for (int mi = 0; mi < 4; mi++)
        #pragma unroll
        for (int ni = 0; ni < 2; ni++)
            #pragma unroll
            for (int q = 0; q < 4; q++) { cU[mi][ni][q] = 0.f; cI[mi][ni][q] = 0.f; }

    const int NCH = 4;           // 128 K / 32

    auto issue = [&](int ch, uint32_t* st) {
        uint32_t sb = smem_u32(st);
        int kc = ch * 16;        // u32 offset
        #pragma unroll
        for (int i = 0; i < 6; i++) {
            int smrow = i * 64 + cr;
            const uint32_t* src;
            if      (i < 2) src = Ab  + (size_t)(i * 64 + cr) * KW;
            else if (i < 4) src = Bmb + (size_t)((i - 2) * 64 + cr) * KW;
            else if (i == 4) src = Wub + (size_t)cr * KW;
            else             src = Wib + (size_t)cr * KW;
            cp16(sb + (uint32_t)(smrow * LDS2 + cc) * 4, src + kc + cc);
        }
    };

    issue(0, smx);
    cp_commit();

    #pragma unroll
    for (int ch = 0; ch < NCH; ch++) {
        cp_wait0();
        __syncthreads();
        if (ch + 1 < NCH) {
            issue(ch + 1, smx + ((ch + 1) & 1) * F_STAGEU);
            cp_commit();
        }
        uint32_t* st  = smx + (ch & 1) * F_STAGEU;
        uint32_t* sA  = st;
        uint32_t* sBm = st + 128 * LDS2;
        uint32_t* sWu = st + 256 * LDS2;
        uint32_t* sWi = st + 320 * LDS2;
        #pragma unroll
        for (int kk = 0; kk < 2; kk++) {
            int kb = kk * 8;
            uint32_t bfu[2][2], bfi[2][2];
            #pragma unroll
            for (int ni = 0; ni < 2; ni++) {
                int n = wn + ni * 8 + g;
                bfu[ni][0] = sWu[n * LDS2 + kb + tig];
                bfu[ni][1] = sWu[n * LDS2 + kb + tig + 4];
                bfi[ni][0] = sWi[n * LDS2 + kb + tig];
                bfi[ni][1] = sWi[n * LDS2 + kb + tig + 4];
            }
            #pragma unroll
            for (int mi = 0; mi < 4; mi++) {
                int r = wm + mi * 16 + g;
                uint32_t aA0 = sA [r * LDS2 + kb + tig];
                uint32_t aA1 = sA [(r + 8) * LDS2 + kb + tig];
                uint32_t aA2 = sA [r * LDS2 + kb + tig + 4];
                uint32_t aA3 = sA [(r + 8) * LDS2 + kb + tig + 4];
                uint32_t aB0 = sBm[r * LDS2 + kb + tig];
                uint32_t aB1 = sBm[(r + 8) * LDS2 + kb + tig];
                uint32_t aB2 = sBm[r * LDS2 + kb + tig + 4];
                uint32_t aB3 = sBm[(r + 8) * LDS2 + kb + tig + 4];
                #pragma unroll
                for (int ni = 0; ni < 2; ni++) {
                    mma_bf16(cU[mi][ni], aA0, aA1, aA2, aA3, bfu[ni][0], bfu[ni][1]);
                    mma_bf16(cI[mi][ni], aB0, aB1, aB2, aB3, bfi[ni][0], bfi[ni][1]);
                }
            }
        }
        __syncthreads();
    }

    // fused combine epilogue -> bf16x2 X
    #pragma unroll
    for (int mi = 0; mi < 4; mi++) {
        int r0 = m0 + wm + mi * 16 + g;
        float d0 = g_Disc[r0], d1 = g_Disc[r0 + 8];
        #pragma unroll
        for (int ni = 0; ni < 2; ni++) {
            int col = n0 + wn + ni * 8 + tig * 2;
            float bu0 = bu[col], bu1 = bu[col + 1];
            float bi0 = bi[col], bi1 = bi[col + 1];
            float x00 = (tanhf(cU[mi][ni][0] + bu0) - sigmoidf(cI[mi][ni][0] + bi0)) * d0;
            float x01 = (tanhf(cU[mi][ni][1] + bu1) - sigmoidf(cI[mi][ni][1] + bi1)) * d0;
            float x10 = (tanhf(cU[mi][ni][2] + bu0) - sigmoidf(cI[mi][ni][2] + bi0)) * d1;
            float x11 = (tanhf(cU[mi][ni][3] + bu1) - sigmoidf(cI[mi][ni][3] + bi1)) * d1;
            g_X2[(size_t)r0 * DHW + (col >> 1)]       = packbf(x00, x01);
            g_X2[(size_t)(r0 + 8) * DHW + (col >> 1)] = packbf(x10, x11);
        }
    }
}

// ---------------- K3: 3-stage bf16 GEMM, H = sigmoid(X@W1^T + b1) ----------------
__global__ void __launch_bounds__(256, 2) k_mlp(const float* __restrict__ bias)
{
    extern __shared__ uint32_t smx[];
    int t = threadIdx.x, lane = t & 31, warp = t >> 5;
    int wm = (warp & 1) * 64;
    int wn = (warp >> 1) * 32;
    int m0 = blockIdx.x * 128, n0 = blockIdx.y * 128;
    int g   = lane >> 2;
    int tig = lane & 3;

    const uint32_t* Ab = g_X2  + (size_t)m0 * DHW;
    const uint32_t* Wb = g_W12 + (size_t)n0 * DHW;

    int cr = t >> 2;
    int cc = (t & 3) * 4;

    float acc[4][4][4];
    #pragma unroll
    for (int mi = 0; mi < 4; mi++)
        #pragma unroll
        for (int ni = 0; ni < 4; ni++)
            #pragma unroll
            for (int q = 0; q < 4; q++) acc[mi][ni][q] = 0.f;

    const int NCH = 16;          // 512 K / 32

    auto issue = [&](int ch, uint32_t* st) {
        uint32_t sb = smem_u32(st);
        int kc = ch * 16;
        #pragma unroll
        for (int i = 0; i < 4; i++) {
            int smrow = i * 64 + cr;
            const uint32_t* src = (i < 2) ? Ab + (size_t)(i * 64 + cr) * DHW
                                          : Wb + (size_t)((i - 2) * 64 + cr) * DHW;
            cp16(sb + (uint32_t)(smrow * LDS2 + cc) * 4, src + kc + cc);
        }
    };

    issue(0, smx);             cp_commit();
    issue(1, smx + M_STAGEU);  cp_commit();

    #pragma unroll 4
    for (int ch = 0; ch < NCH; ch++) {
        cp_wait1();
        __syncthreads();
        if (ch + 2 < NCH) {
            int s2 = (ch + 2) % 3;
            issue(ch + 2, smx + s2 * M_STAGEU);
        }
        cp_commit();
        uint32_t* sA = smx + (ch % 3) * M_STAGEU;
        uint32_t* sW = sA + 128 * LDS2;
        #pragma unroll
        for (int kk = 0; kk < 2; kk++) {
            int kb = kk * 8;
            uint32_t bf[4][2];
            #pragma unroll
            for (int ni = 0; ni < 4; ni++) {
                int n = wn + ni * 8 + g;
                bf[ni][0] = sW[n * LDS2 + kb + tig];
                bf[ni][1] = sW[n * LDS2 + kb + tig + 4];
            }
            #pragma unroll
            for (int mi = 0; mi < 4; mi++) {
                int r = wm + mi * 16 + g;
                uint32_t a0 = sA[r * LDS2 + kb + tig];
                uint32_t a1 = sA[(r + 8) * LDS2 + kb + tig];
                uint32_t a2 = sA[r * LDS2 + kb + tig + 4];
                uint32_t a3 = sA[(r + 8) * LDS2 + kb + tig + 4];
                #pragma unroll
                for (int ni = 0; ni < 4; ni++)
                    mma_bf16(acc[mi][ni], a0, a1, a2, a3, bf[ni][0], bf[ni][1]);
            }
        }
        __syncthreads();
    }

    #pragma unroll
    for (int mi = 0; mi < 4; mi++) {
        int r0 = m0 + wm + mi * 16 + g;
        #pragma unroll
        for (int ni = 0; ni < 4; ni++) {
            int col = n0 + wn + ni * 8 + tig * 2;
            float b0 = bias[col], b1v = bias[col + 1];
            float2 o0, o1;
            o0.x = sigmoidf(acc[mi][ni][0] + b0);
            o0.y = sigmoidf(acc[mi][ni][1] + b1v);
            o1.x = sigmoidf(acc[mi][ni][2] + b0);
            o1.y = sigmoidf(acc[mi][ni][3] + b1v);
            *(float2*)(g_H + (size_t)r0 * H2 + col)       = o0;
            *(float2*)(g_H + (size_t)(r0 + 8) * H2 + col) = o1;
        }
    }
}

// ---------------- K4: final GEMV + sigmoid ----------------
__global__ void k_out(const float* __restrict__ W2, const float* __restrict__ b2,
                      float* __restrict__ out)
{
    int gw   = (blockIdx.x * blockDim.x + threadIdx.x) >> 5;
    int lane = threadIdx.x & 31;
    if (gw >= BATCH) return;
    const float4* h4 = (const float4*)(g_H + (size_t)gw * H2);
    const float4* w4 = (const float4*)W2;
    float s = 0.f;
    #pragma unroll
    for (int i = 0; i < 2; i++) {
        float4 hv = h4[lane + i * 32], wv = w4[lane + i * 32];
        s += hv.x * wv.x + hv.y * wv.y + hv.z * wv.z + hv.w * wv.w;
    }
    #pragma unroll
    for (int o = 16; o; o >>= 1) s += __shfl_xor_sync(0xffffffffu, s, o);
    if (lane == 0) out[gw] = sigmoidf(s + b2[0]);
}

// ---------------- host: numpy-legacy MT19937 graph reconstruction ----------------
namespace {
struct MT { uint32_t mt[624]; int idx; };
static void mt_seed(MT& s, uint32_t seed) {
    s.mt[0] = seed;
    for (int i = 1; i < 624; i++)
        s.mt[i] = 1812433253u * (s.mt[i-1] ^ (s.mt[i-1] >> 30)) + (uint32_t)i;
    s.idx = 624;
}
static uint32_t mt_next(MT& s) {
    if (s.idx >= 624) {
        for (int i = 0; i < 624; i++) {
            uint32_t y = (s.mt[i] & 0x80000000u) | (s.mt[(i+1) % 624] & 0x7fffffffu);
            s.mt[i] = s.mt[(i+397) % 624] ^ (y >> 1) ^ ((y & 1u) ? 0x9908b0dfu : 0u);
        }
        s.idx = 0;
    }
    uint32_t y = s.mt[s.idx++];
    y ^= y >> 11;
    y ^= (y << 7)  & 0x9d2c5680u;
    y ^= (y << 15) & 0xefc60000u;
    y ^= y >> 18;
    return y;
}
static uint32_t draw_bounded(MT& s, uint32_t rng) {
    uint32_t mask = rng; mask |= mask >> 1; mask |= mask >> 2; mask |= mask >> 4;
    mask |= mask >> 8; mask |= mask >> 16;
    uint32_t v;
    do { v = mt_next(s) & mask; } while (v > rng);
    return v;
}
static void build_graph(Sched& sc, int& E) {
    MT mt; mt_seed(mt, 0u);
    int off = 0;
    int level[NC];
    for (int k = 0; k < NC; k++) {
        int l = 0;
        if (k > 0) {
            int hi = (k < 3 ? k : 3) + 1;
            l = (int)draw_bounded(mt, (uint32_t)(hi - 1));
        }
        int preds[3] = {0, 0, 0};
        if (l > 0) {
            int arr[NC];
            for (int i = 0; i < k; i++) arr[i] = i;
            for (int i = k - 1; i >= 1; i--) {
                uint32_t j = draw_bounded(mt, (uint32_t)i);
                int tmp = arr[i]; arr[i] = arr[(int)j]; arr[(int)j] = tmp;
            }
            for (int jj = 0; jj < l; jj++) preds[jj] = arr[jj];
            for (int a = 0; a < l; a++)
                for (int b2_ = a + 1; b2_ < l; b2_++)
                    if (preds[b2_] < preds[a]) { int tm = preds[a]; preds[a] = preds[b2_]; preds[b2_] = tm; }
        }
        sc.lp[k] = (unsigned char)l;
        sc.off[k] = (unsigned short)off;
        sc.invl[k] = (l > 0) ? 1.0f / (float)l : 1.0f;
        for (int jj = 0; jj < 3; jj++) sc.pred[k][jj] = (unsigned char)(jj < l ? preds[jj] : 0);
        int lvl = 0;
        for (int jj = 0; jj < l; jj++) {
            int pl = level[preds[jj]] + 1;
            if (pl > lvl) lvl = pl;
        }
        level[k] = lvl;
        off += l;
    }
    E = off;
    int maxlvl = 0;
    for (int k = 0; k < NC; k++) if (level[k] > maxlvl) maxlvl = level[k];
    sc.nLvl = maxlvl + 1;
    int pos = 0;
    for (int lv = 0; lv <= maxlvl; lv++) {
        sc.lvlStart[lv] = (short)pos;
        for (int k = 0; k < NC; k++)
            if (level[k] == lv) sc.order[pos++] = (unsigned char)k;
    }
    sc.lvlStart[maxlvl + 1] = (short)pos;
}
} // namespace

extern "C" void kernel_launch(void* const* d_in, const int* in_sizes, int n_in,
                              void* d_out, int out_size)
{
    Sched sc; int E;
    build_graph(sc, E);

    const int*   uid    = (const int*)  d_in[0];
    const int*   qid    = (const int*)  d_in[1];
    const float* priori = (const float*)d_in[2];
    const float* cpd    = (const float*)d_in[3];
    const float* cnd    = (const float*)d_in[4];
    const float* idiff  = (const float*)d_in[5];
    const float* idisc  = (const float*)d_in[6];
    const float* qt     = (const float*)d_in[7];
    const float* bu     = (const float*)d_in[9];
    const float* bi     = (const float*)d_in[11];
    const float* b1     = (const float*)d_in[13];
    const float* W2     = (const float*)d_in[14];
    const float* b2     = (const float*)d_in[15];
    float* out = (float*)d_out;

    int Ein = in_sizes[3] / NUM_USER;
    if (Ein > 0 && Ein <= MAXE) E = Ein;

    static bool attr_done = false;
    if (!attr_done) {
        cudaFuncSetAttribute(k_factor, cudaFuncAttributeMaxDynamicSharedMemorySize, SMEM_FACTOR);
        cudaFuncSetAttribute(k_mlp,    cudaFuncAttributeMaxDynamicSharedMemorySize, SMEM_MLP);
        attr_done = true;
    }

    k_prep<<<(H2 * DHW + 255) / 256, 256>>>((const float*)d_in[8], (const float*)d_in[10],
                                            (const float*)d_in[12]);

    k_elem2<<<(BATCH * KW + 255) / 256, 256>>>(qid, idiff, idisc, qt);

    k_mastery2<<<BATCH / WPB, WPB * 32>>>(uid, qid, priori, cpd, cnd, qt, sc, E);

    k_factor<<<dim3(BATCH / 128, DH / 64), 256, SMEM_FACTOR>>>(bu, bi);

    k_mlp<<<dim3(BATCH / 128, H2 / 128), 256, SMEM_MLP>>>(b1);

    k_out<<<(BATCH * 32 + 255) / 256, 256>>>(W2, b2, out);
}

// round 10
// speedup vs baseline: 2.1952x; 1.0287x over previous
#include <cuda_runtime.h>
#include <cuda_bf16.h>
#include <cstdint>

#define NUM_USER     200000
#define NUM_QUESTION 20000
#define NC           128
#define DH           512
#define H2           256
#define BATCH        16384
#define MAXE         384
#define KW           (NC / 2)     // 64 u32 per bf16x2 row (K=128)
#define DHW          (DH / 2)     // 256 u32 per row (K=512)
#define LDS2         20           // smem row stride in u32 (16 data + 4 pad)

// factor stage: A(128)+Bm(128)+Wu(64)+Wi(64) = 384 rows x 20 u32
#define F_STAGEU     (384 * LDS2)
#define SMEM_FACTOR  (2 * F_STAGEU * 4)   // 61440 B
// mlp stage: A(128)+W(128) = 256 rows x 20 u32, 3 stages
#define M_STAGEU     (256 * LDS2)
#define SMEM_MLP     (3 * M_STAGEU * 4)   // 61440 B

// ---------------- scratch (__device__ globals) ----------------
__device__ uint32_t g_Bm2[BATCH * KW];     // bf16x2 packed
__device__ float    g_Disc[BATCH];
__device__ uint32_t g_A2 [BATCH * KW];     // bf16x2 packed
__device__ uint32_t g_X2 [BATCH * DHW];    // bf16x2 packed
__device__ float    g_H  [BATCH * H2];
__device__ uint32_t g_Wu2[DH * KW];
__device__ uint32_t g_Wi2[DH * KW];
__device__ uint32_t g_W12[H2 * DHW];

struct Sched {
    unsigned char  order[NC];
    unsigned char  lp[NC];
    unsigned short off[NC];
    unsigned char  pred[NC][3];
    float          invl[NC];
    short          lvlStart[NC + 1];
    int            nLvl;
};

__device__ __forceinline__ float sigmoidf(float x) {          // exact-ish (mastery/out)
    return __fdividef(1.0f, 1.0f + __expf(-x));
}
__device__ __forceinline__ float tanha(float x) {             // 1 MUFU
    float y;
    asm("tanh.approx.f32 %0, %1;" : "=f"(y) : "f"(x));
    return y;
}
__device__ __forceinline__ float sigma(float x) {             // 1 MUFU + 1 FMA
    return fmaf(tanha(0.5f * x), 0.5f, 0.5f);
}
__device__ __forceinline__ uint32_t packbf(float x, float y) {
    __nv_bfloat162 v = __floats2bfloat162_rn(x, y);
    return *(uint32_t*)&v;
}
__device__ __forceinline__ uint32_t smem_u32(const void* p) {
    uint32_t a;
    asm("{ .reg .u64 t; cvta.to.shared.u64 t, %1; cvt.u32.u64 %0, t; }" : "=r"(a) : "l"(p));
    return a;
}
__device__ __forceinline__ void cp16(uint32_t s, const void* g) {
    asm volatile("cp.async.cg.shared.global [%0], [%1], 16;" :: "r"(s), "l"(g));
}
__device__ __forceinline__ void cp_commit() {
    asm volatile("cp.async.commit_group;" ::: "memory");
}
__device__ __forceinline__ void cp_wait0() {
    asm volatile("cp.async.wait_group 0;" ::: "memory");
}
__device__ __forceinline__ void cp_wait1() {
    asm volatile("cp.async.wait_group 1;" ::: "memory");
}
__device__ __forceinline__ void ldsm4(uint32_t r[4], uint32_t addr) {
    asm volatile("ldmatrix.sync.aligned.m8n8.x4.shared.b16 {%0,%1,%2,%3}, [%4];"
        : "=r"(r[0]), "=r"(r[1]), "=r"(r[2]), "=r"(r[3]) : "r"(addr));
}
__device__ __forceinline__ void mma_bf16(float c[4],
                                         uint32_t a0, uint32_t a1, uint32_t a2, uint32_t a3,
                                         uint32_t b0, uint32_t b1) {
    asm volatile(
        "mma.sync.aligned.m16n8k16.row.col.f32.bf16.bf16.f32 "
        "{%0,%1,%2,%3}, {%4,%5,%6,%7}, {%8,%9}, {%0,%1,%2,%3};"
        : "+f"(c[0]), "+f"(c[1]), "+f"(c[2]), "+f"(c[3])
        : "r"(a0), "r"(a1), "r"(a2), "r"(a3), "r"(b0), "r"(b1));
}

// ---------------- K-1: pack weights to bf16x2 ----------------
__global__ void k_prep(const float* __restrict__ Wu, const float* __restrict__ Wi,
                       const float* __restrict__ W1)
{
    int i = blockIdx.x * blockDim.x + threadIdx.x;
    if (i < DH * KW) {
        g_Wu2[i] = packbf(Wu[2 * i], Wu[2 * i + 1]);
        g_Wi2[i] = packbf(Wi[2 * i], Wi[2 * i + 1]);
    }
    if (i < H2 * DHW)
        g_W12[i] = packbf(W1[2 * i], W1[2 * i + 1]);
}

// ---------------- K0: Bm / disc ----------------
__global__ void k_elem2(const int* __restrict__ qid,
                        const float* __restrict__ idiff, const float* __restrict__ idisc,
                        const float* __restrict__ qt)
{
    int idx = blockIdx.x * blockDim.x + threadIdx.x;
    if (idx >= BATCH * KW) return;
    int b = idx >> 6, j = idx & 63;
    int q = qid[b];
    size_t base = (size_t)q * NC + 2 * j;
    float v0 = sigma(idiff[base])     * qt[base];
    float v1 = sigma(idiff[base + 1]) * qt[base + 1];
    g_Bm2[idx] = packbf(v0, v1);
    if (j == 0) g_Disc[b] = sigma(idisc[q]);
}

// ---------------- K1: fused warp-per-row level-parallel posterior ----------------
#define WPB 8
__global__ void __launch_bounds__(WPB * 32) k_mastery2(
    const int* __restrict__ uid, const int* __restrict__ qid,
    const float* __restrict__ priori,
    const float* __restrict__ condi_p, const float* __restrict__ condi_n,
    const float* __restrict__ qt, Sched s, int E)
{
    __shared__ float sm_m [WPB][NC];
    __shared__ float sm_cp[WPB][MAXE];
    __shared__ float sm_cn[WPB][MAXE];

    int lane = threadIdx.x & 31, w = threadIdx.x >> 5;
    int b = blockIdx.x * WPB + w;
    int u = uid[b];

    const float* cpr = condi_p + (size_t)u * E;
    const float* cnr = condi_n + (size_t)u * E;
    for (int j = lane; j < E; j += 32) {
        sm_cp[w][j] = sigmoidf(cpr[j]);
        sm_cn[w][j] = sigmoidf(cnr[j]);
    }
    __syncwarp();

    const float* pr = priori + (size_t)u * NC;
    for (int lv = 0; lv < s.nLvl; lv++) {
        int e = s.lvlStart[lv + 1];
        for (int i = s.lvlStart[lv] + lane; i < e; i += 32) {
            int k = s.order[i];
            int l = s.lp[k];
            float v;
            if (l == 0) {
                v = sigmoidf(pr[k]);
            } else {
                int o = s.off[k];
                float inv = s.invl[k];
                v = 1.0f;
                #pragma unroll 1
                for (int j = 0; j < l; j++) {
                    float mp = sm_m[w][s.pred[k][j]];
                    float a = sm_cp[w][o + j], bb = sm_cn[w][o + j];
                    if (l > 1) { a = __powf(a, inv); bb = __powf(bb, inv); }
                    v *= a * mp + bb * (1.0f - mp);
                }
            }
            sm_m[w][k] = v;
        }
        __syncwarp();
    }

    int q = qid[b];
    const float* qr = qt + (size_t)q * NC;
    uint32_t* ao = g_A2 + (size_t)b * KW;
    for (int j = lane; j < KW; j += 32)
        ao[j] = packbf(sm_m[w][2 * j] * qr[2 * j], sm_m[w][2 * j + 1] * qr[2 * j + 1]);
}

// ---------------- K2: fused dual bf16 GEMM -> X  (CTA 128M x 64N, BK=32) ----------------
// X = (tanh(A@Wu^T + bu) - sigmoid(Bm@Wi^T + bi)) * disc   -> stored bf16x2
// smem stage rows: [0,128)=A  [128,256)=Bm  [256,320)=Wu  [320,384)=Wi
__global__ void __launch_bounds__(256, 2) k_factor(const float* __restrict__ bu,
                                                   const float* __restrict__ bi)
{
    extern __shared__ uint32_t smx[];
    int t = threadIdx.x, lane = t & 31, warp = t >> 5;
    int wm = (warp & 1) * 64;
    int wn = (warp >> 1) * 16;
    int m0 = blockIdx.x * 128, n0 = blockIdx.y * 64;
    int g   = lane >> 2;
    int tig = lane & 3;
    int lr  = lane & 15;          // ldmatrix row-in-16
    int lk  = (lane >> 4) * 4;    // ldmatrix k-half (u32)

    const uint32_t* Ab  = g_A2  + (size_t)m0 * KW;
    const uint32_t* Bmb = g_Bm2 + (size_t)m0 * KW;
    const uint32_t* Wub = g_Wu2 + (size_t)n0 * KW;
    const uint32_t* Wib = g_Wi2 + (size_t)n0 * KW;

    int cr = t >> 2;              // 0..63
    int cc = (t & 3) * 4;         // u32 col: 0,4,8,12

    float cU[4][2][4], cI[4][2][4];
    #pragma unroll
    for (int mi = 0; mi < 4; mi++)
        #pragma unroll
        for (int ni = 0; ni < 2; ni++)
            #pragma unroll
            for (int q = 0; q < 4; q++) { cU[mi][ni][q] = 0.f; cI[mi][ni][q] = 0.f; }

    const int NCH = 4;            // 128 K / 32

    auto issue = [&](int ch, uint32_t* st) {
        uint32_t sb = smem_u32(st);
        int kc = ch * 16;         // u32 offset
        #pragma unroll
        for (int i = 0; i < 6; i++) {
            int smrow = i * 64 + cr;
            const uint32_t* src;
            if      (i < 2) src = Ab  + (size_t)(i * 64 + cr) * KW;
            else if (i < 4) src = Bmb + (size_t)((i - 2) * 64 + cr) * KW;
            else if (i == 4) src = Wub + (size_t)cr * KW;
            else             src = Wib + (size_t)cr * KW;
            cp16(sb + (uint32_t)(smrow * LDS2 + cc) * 4, src + kc + cc);
        }
    };

    issue(0, smx);
    cp_commit();

    #pragma unroll
    for (int ch = 0; ch < NCH; ch++) {
        cp_wait0();
        __syncthreads();
        if (ch + 1 < NCH) {
            issue(ch + 1, smx + ((ch + 1) & 1) * F_STAGEU);
            cp_commit();
        }
        uint32_t sb = smem_u32(smx + (ch & 1) * F_STAGEU);
        #pragma unroll
        for (int kk = 0; kk < 2; kk++) {
            int kb = kk * 8;
            // B frags for both ni via one x4 each
            uint32_t fu[4], fi[4];   // {b0(ni0), b0(ni1), b1(ni0), b1(ni1)}
            ldsm4(fu, sb + 4u * ((256 + wn + lr) * LDS2 + kb + lk));
            ldsm4(fi, sb + 4u * ((320 + wn + lr) * LDS2 + kb + lk));
            #pragma unroll
            for (int mi = 0; mi < 4; mi++) {
                int rb = wm + mi * 16 + lr;
                uint32_t aA[4], aB[4];
                ldsm4(aA, sb + 4u * (rb * LDS2 + kb + lk));
                ldsm4(aB, sb + 4u * ((128 + rb) * LDS2 + kb + lk));
                mma_bf16(cU[mi][0], aA[0], aA[1], aA[2], aA[3], fu[0], fu[2]);
                mma_bf16(cU[mi][1], aA[0], aA[1], aA[2], aA[3], fu[1], fu[3]);
                mma_bf16(cI[mi][0], aB[0], aB[1], aB[2], aB[3], fi[0], fi[2]);
                mma_bf16(cI[mi][1], aB[0], aB[1], aB[2], aB[3], fi[1], fi[3]);
            }
        }
        __syncthreads();
    }

    // fused combine epilogue -> bf16x2 X (tanh.approx based)
    #pragma unroll
    for (int mi = 0; mi < 4; mi++) {
        int r0 = m0 + wm + mi * 16 + g;
        float d0 = g_Disc[r0], d1 = g_Disc[r0 + 8];
        #pragma unroll
        for (int ni = 0; ni < 2; ni++) {
            int col = n0 + wn + ni * 8 + tig * 2;
            float bu0 = bu[col], bu1 = bu[col + 1];
            float bi0 = bi[col], bi1 = bi[col + 1];
            float x00 = (tanha(cU[mi][ni][0] + bu0) - sigma(cI[mi][ni][0] + bi0)) * d0;
            float x01 = (tanha(cU[mi][ni][1] + bu1) - sigma(cI[mi][ni][1] + bi1)) * d0;
            float x10 = (tanha(cU[mi][ni][2] + bu0) - sigma(cI[mi][ni][2] + bi0)) * d1;
            float x11 = (tanha(cU[mi][ni][3] + bu1) - sigma(cI[mi][ni][3] + bi1)) * d1;
            g_X2[(size_t)r0 * DHW + (col >> 1)]       = packbf(x00, x01);
            g_X2[(size_t)(r0 + 8) * DHW + (col >> 1)] = packbf(x10, x11);
        }
    }
}

// ---------------- K3: 3-stage bf16 GEMM, H = sigmoid(X@W1^T + b1) ----------------
__global__ void __launch_bounds__(256, 2) k_mlp(const float* __restrict__ bias)
{
    extern __shared__ uint32_t smx[];
    int t = threadIdx.x, lane = t & 31, warp = t >> 5;
    int wm = (warp & 1) * 64;
    int wn = (warp >> 1) * 32;
    int m0 = blockIdx.x * 128, n0 = blockIdx.y * 128;
    int g   = lane >> 2;
    int tig = lane & 3;
    int lr  = lane & 15;
    int lk  = (lane >> 4) * 4;

    const uint32_t* Ab = g_X2  + (size_t)m0 * DHW;
    const uint32_t* Wb = g_W12 + (size_t)n0 * DHW;

    int cr = t >> 2;
    int cc = (t & 3) * 4;

    float acc[4][4][4];
    #pragma unroll
    for (int mi = 0; mi < 4; mi++)
        #pragma unroll
        for (int ni = 0; ni < 4; ni++)
            #pragma unroll
            for (int q = 0; q < 4; q++) acc[mi][ni][q] = 0.f;

    const int NCH = 16;           // 512 K / 32

    auto issue = [&](int ch, uint32_t* st) {
        uint32_t sb = smem_u32(st);
        int kc = ch * 16;
        #pragma unroll
        for (int i = 0; i < 4; i++) {
            int smrow = i * 64 + cr;
            const uint32_t* src = (i < 2) ? Ab + (size_t)(i * 64 + cr) * DHW
                                          : Wb + (size_t)((i - 2) * 64 + cr) * DHW;
            cp16(sb + (uint32_t)(smrow * LDS2 + cc) * 4, src + kc + cc);
        }
    };

    issue(0, smx);             cp_commit();
    issue(1, smx + M_STAGEU);  cp_commit();

    #pragma unroll 4
    for (int ch = 0; ch < NCH; ch++) {
        cp_wait1();
        __syncthreads();
        if (ch + 2 < NCH) {
            int s2 = (ch + 2) % 3;
            issue(ch + 2, smx + s2 * M_STAGEU);
        }
        cp_commit();
        uint32_t sb = smem_u32(smx + (ch % 3) * M_STAGEU);
        #pragma unroll
        for (int kk = 0; kk < 2; kk++) {
            int kb = kk * 8;
            uint32_t f0[4], f1[4];   // B frags: ni0/1 and ni2/3
            ldsm4(f0, sb + 4u * ((128 + wn + lr) * LDS2 + kb + lk));
            ldsm4(f1, sb + 4u * ((144 + wn + lr) * LDS2 + kb + lk));
            #pragma unroll
            for (int mi = 0; mi < 4; mi++) {
                int rb = wm + mi * 16 + lr;
                uint32_t a[4];
                ldsm4(a, sb + 4u * (rb * LDS2 + kb + lk));
                mma_bf16(acc[mi][0], a[0], a[1], a[2], a[3], f0[0], f0[2]);
                mma_bf16(acc[mi][1], a[0], a[1], a[2], a[3], f0[1], f0[3]);
                mma_bf16(acc[mi][2], a[0], a[1], a[2], a[3], f1[0], f1[2]);
                mma_bf16(acc[mi][3], a[0], a[1], a[2], a[3], f1[1], f1[3]);
            }
        }
        __syncthreads();
    }

    #pragma unroll
    for (int mi = 0; mi < 4; mi++) {
        int r0 = m0 + wm + mi * 16 + g;
        #pragma unroll
        for (int ni = 0; ni < 4; ni++) {
            int col = n0 + wn + ni * 8 + tig * 2;
            float b0 = bias[col], b1v = bias[col + 1];
            float2 o0, o1;
            o0.x = sigma(acc[mi][ni][0] + b0);
            o0.y = sigma(acc[mi][ni][1] + b1v);
            o1.x = sigma(acc[mi][ni][2] + b0);
            o1.y = sigma(acc[mi][ni][3] + b1v);
            *(float2*)(g_H + (size_t)r0 * H2 + col)       = o0;
            *(float2*)(g_H + (size_t)(r0 + 8) * H2 + col) = o1;
        }
    }
}

// ---------------- K4: final GEMV + sigmoid ----------------
__global__ void k_out(const float* __restrict__ W2, const float* __restrict__ b2,
                      float* __restrict__ out)
{
    int gw   = (blockIdx.x * blockDim.x + threadIdx.x) >> 5;
    int lane = threadIdx.x & 31;
    if (gw >= BATCH) return;
    const float4* h4 = (const float4*)(g_H + (size_t)gw * H2);
    const float4* w4 = (const float4*)W2;
    float s = 0.f;
    #pragma unroll
    for (int i = 0; i < 2; i++) {
        float4 hv = h4[lane + i * 32], wv = w4[lane + i * 32];
        s += hv.x * wv.x + hv.y * wv.y + hv.z * wv.z + hv.w * wv.w;
    }
    #pragma unroll
    for (int o = 16; o; o >>= 1) s += __shfl_xor_sync(0xffffffffu, s, o);
    if (lane == 0) out[gw] = sigmoidf(s + b2[0]);
}

// ---------------- host: numpy-legacy MT19937 graph reconstruction ----------------
namespace {
struct MT { uint32_t mt[624]; int idx; };
static void mt_seed(MT& s, uint32_t seed) {
    s.mt[0] = seed;
    for (int i = 1; i < 624; i++)
        s.mt[i] = 1812433253u * (s.mt[i-1] ^ (s.mt[i-1] >> 30)) + (uint32_t)i;
    s.idx = 624;
}
static uint32_t mt_next(MT& s) {
    if (s.idx >= 624) {
        for (int i = 0; i < 624; i++) {
            uint32_t y = (s.mt[i] & 0x80000000u) | (s.mt[(i+1) % 624] & 0x7fffffffu);
            s.mt[i] = s.mt[(i+397) % 624] ^ (y >> 1) ^ ((y & 1u) ? 0x9908b0dfu : 0u);
        }
        s.idx = 0;
    }
    uint32_t y = s.mt[s.idx++];
    y ^= y >> 11;
    y ^= (y << 7)  & 0x9d2c5680u;
    y ^= (y << 15) & 0xefc60000u;
    y ^= y >> 18;
    return y;
}
static uint32_t draw_bounded(MT& s, uint32_t rng) {
    uint32_t mask = rng; mask |= mask >> 1; mask |= mask >> 2; mask |= mask >> 4;
    mask |= mask >> 8; mask |= mask >> 16;
    uint32_t v;
    do { v = mt_next(s) & mask; } while (v > rng);
    return v;
}
static void build_graph(Sched& sc, int& E) {
    MT mt; mt_seed(mt, 0u);
    int off = 0;
    int level[NC];
    for (int k = 0; k < NC; k++) {
        int l = 0;
        if (k > 0) {
            int hi = (k < 3 ? k : 3) + 1;
            l = (int)draw_bounded(mt, (uint32_t)(hi - 1));
        }
        int preds[3] = {0, 0, 0};
        if (l > 0) {
            int arr[NC];
            for (int i = 0; i < k; i++) arr[i] = i;
            for (int i = k - 1; i >= 1; i--) {
                uint32_t j = draw_bounded(mt, (uint32_t)i);
                int tmp = arr[i]; arr[i] = arr[(int)j]; arr[(int)j] = tmp;
            }
            for (int jj = 0; jj < l; jj++) preds[jj] = arr[jj];
            for (int a = 0; a < l; a++)
                for (int b2_ = a + 1; b2_ < l; b2_++)
                    if (preds[b2_] < preds[a]) { int tm = preds[a]; preds[a] = preds[b2_]; preds[b2_] = tm; }
        }
        sc.lp[k] = (unsigned char)l;
        sc.off[k] = (unsigned short)off;
        sc.invl[k] = (l > 0) ? 1.0f / (float)l : 1.0f;
        for (int jj = 0; jj < 3; jj++) sc.pred[k][jj] = (unsigned char)(jj < l ? preds[jj] : 0);
        int lvl = 0;
        for (int jj = 0; jj < l; jj++) {
            int pl = level[preds[jj]] + 1;
            if (pl > lvl) lvl = pl;
        }
        level[k] = lvl;
        off += l;
    }
    E = off;
    int maxlvl = 0;
    for (int k = 0; k < NC; k++) if (level[k] > maxlvl) maxlvl = level[k];
    sc.nLvl = maxlvl + 1;
    int pos = 0;
    for (int lv = 0; lv <= maxlvl; lv++) {
        sc.lvlStart[lv] = (short)pos;
        for (int k = 0; k < NC; k++)
            if (level[k] == lv) sc.order[pos++] = (unsigned char)k;
    }
    sc.lvlStart[maxlvl + 1] = (short)pos;
}
} // namespace

extern "C" void kernel_launch(void* const* d_in, const int* in_sizes, int n_in,
                              void* d_out, int out_size)
{
    Sched sc; int E;
    build_graph(sc, E);

    const int*   uid    = (const int*)  d_in[0];
    const int*   qid    = (const int*)  d_in[1];
    const float* priori = (const float*)d_in[2];
    const float* cpd    = (const float*)d_in[3];
    const float* cnd    = (const float*)d_in[4];
    const float* idiff  = (const float*)d_in[5];
    const float* idisc  = (const float*)d_in[6];
    const float* qt     = (const float*)d_in[7];
    const float* bu     = (const float*)d_in[9];
    const float* bi     = (const float*)d_in[11];
    const float* b1     = (const float*)d_in[13];
    const float* W2     = (const float*)d_in[14];
    const float* b2     = (const float*)d_in[15];
    float* out = (float*)d_out;

    int Ein = in_sizes[3] / NUM_USER;
    if (Ein > 0 && Ein <= MAXE) E = Ein;

    static bool attr_done = false;
    if (!attr_done) {
        cudaFuncSetAttribute(k_factor, cudaFuncAttributeMaxDynamicSharedMemorySize, SMEM_FACTOR);
        cudaFuncSetAttribute(k_mlp,    cudaFuncAttributeMaxDynamicSharedMemorySize, SMEM_MLP);
        attr_done = true;
    }

    k_prep<<<(H2 * DHW + 255) / 256, 256>>>((const float*)d_in[8], (const float*)d_in[10],
                                            (const float*)d_in[12]);

    k_elem2<<<(BATCH * KW + 255) / 256, 256>>>(qid, idiff, idisc, qt);

    k_mastery2<<<BATCH / WPB, WPB * 32>>>(uid, qid, priori, cpd, cnd, qt, sc, E);

    k_factor<<<dim3(BATCH / 128, DH / 64), 256, SMEM_FACTOR>>>(bu, bi);

    k_mlp<<<dim3(BATCH / 128, H2 / 128), 256, SMEM_MLP>>>(b1);

    k_out<<<(BATCH * 32 + 255) / 256, 256>>>(W2, b2, out);
}

// round 11
// speedup vs baseline: 2.3614x; 1.0757x over previous
#include <cuda_runtime.h>
#include <cuda_bf16.h>
#include <cstdint>

#define NUM_USER     200000
#define NUM_QUESTION 20000
#define NC           128
#define DH           512
#define H2           256
#define BATCH        16384
#define MAXE         384
#define KW           (NC / 2)     // 64 u32 per bf16x2 row (K=128)
#define DHW          (DH / 2)     // 256 u32 per row (K=512)
#define LDS2         36           // smem row stride in u32 (32 data + 4 pad), BK=64

// factor stage: A(128)+Bm(128)+Wu(64)+Wi(64) = 384 rows x 36 u32, 2 stages
#define F_STAGEU     (384 * LDS2)
#define SMEM_FACTOR  (2 * F_STAGEU * 4)   // 110592 B
// mlp stage: A(128)+W(128) = 256 rows x 36 u32, 3 stages
#define M_STAGEU     (256 * LDS2)
#define SMEM_MLP     (3 * M_STAGEU * 4)   // 110592 B

// ---------------- scratch (__device__ globals) ----------------
__device__ uint32_t g_Bm2[BATCH * KW];     // bf16x2 packed
__device__ float    g_Disc[BATCH];
__device__ uint32_t g_A2 [BATCH * KW];     // bf16x2 packed
__device__ uint32_t g_X2 [BATCH * DHW];    // bf16x2 packed
__device__ float    g_P  [2 * BATCH];      // per-half GEMV partials
__device__ uint32_t g_Wu2[DH * KW];
__device__ uint32_t g_Wi2[DH * KW];
__device__ uint32_t g_W12[H2 * DHW];

struct Sched {
    unsigned char  order[NC];
    unsigned char  lp[NC];
    unsigned short off[NC];
    unsigned char  pred[NC][3];
    float          invl[NC];
    short          lvlStart[NC + 1];
    int            nLvl;
};

__device__ __forceinline__ float sigmoidf(float x) {          // exact-ish (mastery/fin)
    return __fdividef(1.0f, 1.0f + __expf(-x));
}
__device__ __forceinline__ float tanha(float x) {             // 1 MUFU
    float y;
    asm("tanh.approx.f32 %0, %1;" : "=f"(y) : "f"(x));
    return y;
}
__device__ __forceinline__ float sigma(float x) {             // 1 MUFU + 1 FMA
    return fmaf(tanha(0.5f * x), 0.5f, 0.5f);
}
__device__ __forceinline__ uint32_t packbf(float x, float y) {
    __nv_bfloat162 v = __floats2bfloat162_rn(x, y);
    return *(uint32_t*)&v;
}
__device__ __forceinline__ uint32_t smem_u32(const void* p) {
    uint32_t a;
    asm("{ .reg .u64 t; cvta.to.shared.u64 t, %1; cvt.u32.u64 %0, t; }" : "=r"(a) : "l"(p));
    return a;
}
__device__ __forceinline__ void cp16(uint32_t s, const void* g) {
    asm volatile("cp.async.cg.shared.global [%0], [%1], 16;" :: "r"(s), "l"(g));
}
__device__ __forceinline__ void cp_commit() {
    asm volatile("cp.async.commit_group;" ::: "memory");
}
__device__ __forceinline__ void cp_wait0() {
    asm volatile("cp.async.wait_group 0;" ::: "memory");
}
__device__ __forceinline__ void cp_wait1() {
    asm volatile("cp.async.wait_group 1;" ::: "memory");
}
__device__ __forceinline__ void ldsm4(uint32_t r[4], uint32_t addr) {
    asm volatile("ldmatrix.sync.aligned.m8n8.x4.shared.b16 {%0,%1,%2,%3}, [%4];"
        : "=r"(r[0]), "=r"(r[1]), "=r"(r[2]), "=r"(r[3]) : "r"(addr));
}
__device__ __forceinline__ void mma_bf16(float c[4],
                                         uint32_t a0, uint32_t a1, uint32_t a2, uint32_t a3,
                                         uint32_t b0, uint32_t b1) {
    asm volatile(
        "mma.sync.aligned.m16n8k16.row.col.f32.bf16.bf16.f32 "
        "{%0,%1,%2,%3}, {%4,%5,%6,%7}, {%8,%9}, {%0,%1,%2,%3};"
        : "+f"(c[0]), "+f"(c[1]), "+f"(c[2]), "+f"(c[3])
        : "r"(a0), "r"(a1), "r"(a2), "r"(a3), "r"(b0), "r"(b1));
}

// ---------------- K0: weights pack + Bm / disc (merged) ----------------
__global__ void k_pre(const int* __restrict__ qid,
                      const float* __restrict__ idiff, const float* __restrict__ idisc,
                      const float* __restrict__ qt,
                      const float* __restrict__ Wu, const float* __restrict__ Wi,
                      const float* __restrict__ W1)
{
    int idx = blockIdx.x * blockDim.x + threadIdx.x;
    if (idx >= BATCH * KW) return;
    if (idx < DH * KW) {
        g_Wu2[idx] = packbf(Wu[2 * idx], Wu[2 * idx + 1]);
        g_Wi2[idx] = packbf(Wi[2 * idx], Wi[2 * idx + 1]);
    }
    if (idx < H2 * DHW)
        g_W12[idx] = packbf(W1[2 * idx], W1[2 * idx + 1]);
    int b = idx >> 6, j = idx & 63;
    int q = qid[b];
    size_t base = (size_t)q * NC + 2 * j;
    float v0 = sigma(idiff[base])     * qt[base];
    float v1 = sigma(idiff[base + 1]) * qt[base + 1];
    g_Bm2[idx] = packbf(v0, v1);
    if (j == 0) g_Disc[b] = sigma(idisc[q]);
}

// ---------------- K1: fused warp-per-row level-parallel posterior ----------------
#define WPB 8
__global__ void __launch_bounds__(WPB * 32) k_mastery2(
    const int* __restrict__ uid, const int* __restrict__ qid,
    const float* __restrict__ priori,
    const float* __restrict__ condi_p, const float* __restrict__ condi_n,
    const float* __restrict__ qt, Sched s, int E)
{
    __shared__ float sm_m [WPB][NC];
    __shared__ float sm_cp[WPB][MAXE];
    __shared__ float sm_cn[WPB][MAXE];

    int lane = threadIdx.x & 31, w = threadIdx.x >> 5;
    int b = blockIdx.x * WPB + w;
    int u = uid[b];

    const float* cpr = condi_p + (size_t)u * E;
    const float* cnr = condi_n + (size_t)u * E;
    for (int j = lane; j < E; j += 32) {
        sm_cp[w][j] = sigmoidf(cpr[j]);
        sm_cn[w][j] = sigmoidf(cnr[j]);
    }
    __syncwarp();

    const float* pr = priori + (size_t)u * NC;
    for (int lv = 0; lv < s.nLvl; lv++) {
        int e = s.lvlStart[lv + 1];
        for (int i = s.lvlStart[lv] + lane; i < e; i += 32) {
            int k = s.order[i];
            int l = s.lp[k];
            float v;
            if (l == 0) {
                v = sigmoidf(pr[k]);
            } else {
                int o = s.off[k];
                float inv = s.invl[k];
                v = 1.0f;
                #pragma unroll 1
                for (int j = 0; j < l; j++) {
                    float mp = sm_m[w][s.pred[k][j]];
                    float a = sm_cp[w][o + j], bb = sm_cn[w][o + j];
                    if (l > 1) { a = __powf(a, inv); bb = __powf(bb, inv); }
                    v *= a * mp + bb * (1.0f - mp);
                }
            }
            sm_m[w][k] = v;
        }
        __syncwarp();
    }

    int q = qid[b];
    const float* qr = qt + (size_t)q * NC;
    uint32_t* ao = g_A2 + (size_t)b * KW;
    for (int j = lane; j < KW; j += 32)
        ao[j] = packbf(sm_m[w][2 * j] * qr[2 * j], sm_m[w][2 * j + 1] * qr[2 * j + 1]);
}

// ---------------- K2: fused dual bf16 GEMM -> X  (CTA 128M x 64N, BK=64) ----------------
// smem stage rows: [0,128)=A  [128,256)=Bm  [256,320)=Wu  [320,384)=Wi
__global__ void __launch_bounds__(256, 2) k_factor(const float* __restrict__ bu,
                                                   const float* __restrict__ bi)
{
    extern __shared__ uint32_t smx[];
    int t = threadIdx.x, lane = t & 31, warp = t >> 5;
    int wm = (warp & 1) * 64;
    int wn = (warp >> 1) * 16;
    int m0 = blockIdx.x * 128, n0 = blockIdx.y * 64;
    int g   = lane >> 2;
    int tig = lane & 3;
    int lr  = lane & 15;
    int lk  = (lane >> 4) * 4;

    const uint32_t* Ab  = g_A2  + (size_t)m0 * KW;
    const uint32_t* Bmb = g_Bm2 + (size_t)m0 * KW;
    const uint32_t* Wub = g_Wu2 + (size_t)n0 * KW;
    const uint32_t* Wib = g_Wi2 + (size_t)n0 * KW;

    int cr = t >> 3;              // row 0..31
    int cc = (t & 7) * 4;         // u32 col 0..28

    float cU[4][2][4], cI[4][2][4];
    #pragma unroll
    for (int mi = 0; mi < 4; mi++)
        #pragma unroll
        for (int ni = 0; ni < 2; ni++)
            #pragma unroll
            for (int q = 0; q < 4; q++) { cU[mi][ni][q] = 0.f; cI[mi][ni][q] = 0.f; }

    const int NCH = 2;            // 128 K / 64

    auto issue = [&](int ch, uint32_t* st) {
        uint32_t sb = smem_u32(st);
        int kc = ch * 32;         // u32 offset
        #pragma unroll
        for (int i = 0; i < 12; i++) {
            int smrow = i * 32 + cr;
            const uint32_t* src;
            if      (i < 4)  src = Ab  + (size_t)(i * 32 + cr) * KW;
            else if (i < 8)  src = Bmb + (size_t)((i - 4) * 32 + cr) * KW;
            else if (i < 10) src = Wub + (size_t)((i - 8) * 32 + cr) * KW;
            else             src = Wib + (size_t)((i - 10) * 32 + cr) * KW;
            cp16(sb + (uint32_t)(smrow * LDS2 + cc) * 4, src + kc + cc);
        }
    };

    issue(0, smx);
    cp_commit();

    #pragma unroll
    for (int ch = 0; ch < NCH; ch++) {
        cp_wait0();
        __syncthreads();
        if (ch + 1 < NCH) {
            issue(ch + 1, smx + ((ch + 1) & 1) * F_STAGEU);
            cp_commit();
        }
        uint32_t sb = smem_u32(smx + (ch & 1) * F_STAGEU);
        #pragma unroll
        for (int kk = 0; kk < 4; kk++) {
            int kb = kk * 8;
            uint32_t fu[4], fi[4];
            ldsm4(fu, sb + 4u * ((256 + wn + lr) * LDS2 + kb + lk));
            ldsm4(fi, sb + 4u * ((320 + wn + lr) * LDS2 + kb + lk));
            #pragma unroll
            for (int mi = 0; mi < 4; mi++) {
                int rb = wm + mi * 16 + lr;
                uint32_t aA[4], aB[4];
                ldsm4(aA, sb + 4u * (rb * LDS2 + kb + lk));
                ldsm4(aB, sb + 4u * ((128 + rb) * LDS2 + kb + lk));
                mma_bf16(cU[mi][0], aA[0], aA[1], aA[2], aA[3], fu[0], fu[2]);
                mma_bf16(cU[mi][1], aA[0], aA[1], aA[2], aA[3], fu[1], fu[3]);
                mma_bf16(cI[mi][0], aB[0], aB[1], aB[2], aB[3], fi[0], fi[2]);
                mma_bf16(cI[mi][1], aB[0], aB[1], aB[2], aB[3], fi[1], fi[3]);
            }
        }
        __syncthreads();
    }

    // fused combine epilogue -> bf16x2 X
    #pragma unroll
    for (int mi = 0; mi < 4; mi++) {
        int r0 = m0 + wm + mi * 16 + g;
        float d0 = g_Disc[r0], d1 = g_Disc[r0 + 8];
        #pragma unroll
        for (int ni = 0; ni < 2; ni++) {
            int col = n0 + wn + ni * 8 + tig * 2;
            float bu0 = bu[col], bu1 = bu[col + 1];
            float bi0 = bi[col], bi1 = bi[col + 1];
            float x00 = (tanha(cU[mi][ni][0] + bu0) - sigma(cI[mi][ni][0] + bi0)) * d0;
            float x01 = (tanha(cU[mi][ni][1] + bu1) - sigma(cI[mi][ni][1] + bi1)) * d0;
            float x10 = (tanha(cU[mi][ni][2] + bu0) - sigma(cI[mi][ni][2] + bi0)) * d1;
            float x11 = (tanha(cU[mi][ni][3] + bu1) - sigma(cI[mi][ni][3] + bi1)) * d1;
            g_X2[(size_t)r0 * DHW + (col >> 1)]       = packbf(x00, x01);
            g_X2[(size_t)(r0 + 8) * DHW + (col >> 1)] = packbf(x10, x11);
        }
    }
}

// ---------------- K3: bf16 GEMM + fused GEMV partials (BK=64, 3-stage) ----------------
// H = sigmoid(X@W1^T + b1) computed in registers; partial = H_tile . W2_slice
// -> g_P[blockIdx.y][row]
__global__ void __launch_bounds__(256, 2) k_mlp(const float* __restrict__ bias,
                                                const float* __restrict__ W2)
{
    extern __shared__ uint32_t smx[];
    int t = threadIdx.x, lane = t & 31, warp = t >> 5;
    int wm = (warp & 1) * 64;
    int wn = (warp >> 1) * 32;
    int m0 = blockIdx.x * 128, n0 = blockIdx.y * 128;
    int g   = lane >> 2;
    int tig = lane & 3;
    int lr  = lane & 15;
    int lk  = (lane >> 4) * 4;

    const uint32_t* Ab = g_X2  + (size_t)m0 * DHW;
    const uint32_t* Wb = g_W12 + (size_t)n0 * DHW;

    int cr = t >> 3;
    int cc = (t & 7) * 4;

    float acc[4][4][4];
    #pragma unroll
    for (int mi = 0; mi < 4; mi++)
        #pragma unroll
        for (int ni = 0; ni < 4; ni++)
            #pragma unroll
            for (int q = 0; q < 4; q++) acc[mi][ni][q] = 0.f;

    const int NCH = 8;            // 512 K / 64

    auto issue = [&](int ch, uint32_t* st) {
        uint32_t sb = smem_u32(st);
        int kc = ch * 32;
        #pragma unroll
        for (int i = 0; i < 8; i++) {
            int smrow = i * 32 + cr;
            const uint32_t* src = (i < 4) ? Ab + (size_t)(i * 32 + cr) * DHW
                                          : Wb + (size_t)((i - 4) * 32 + cr) * DHW;
            cp16(sb + (uint32_t)(smrow * LDS2 + cc) * 4, src + kc + cc);
        }
    };

    issue(0, smx);             cp_commit();
    issue(1, smx + M_STAGEU);  cp_commit();

    #pragma unroll 2
    for (int ch = 0; ch < NCH; ch++) {
        cp_wait1();
        __syncthreads();
        if (ch + 2 < NCH) {
            int s2 = (ch + 2) % 3;
            issue(ch + 2, smx + s2 * M_STAGEU);
        }
        cp_commit();
        uint32_t sb = smem_u32(smx + (ch % 3) * M_STAGEU);
        #pragma unroll
        for (int kk = 0; kk < 4; kk++) {
            int kb = kk * 8;
            uint32_t f0[4], f1[4];
            ldsm4(f0, sb + 4u * ((128 + wn + lr) * LDS2 + kb + lk));
            ldsm4(f1, sb + 4u * ((144 + wn + lr) * LDS2 + kb + lk));
            #pragma unroll
            for (int mi = 0; mi < 4; mi++) {
                int rb = wm + mi * 16 + lr;
                uint32_t a[4];
                ldsm4(a, sb + 4u * (rb * LDS2 + kb + lk));
                mma_bf16(acc[mi][0], a[0], a[1], a[2], a[3], f0[0], f0[2]);
                mma_bf16(acc[mi][1], a[0], a[1], a[2], a[3], f0[1], f0[3]);
                mma_bf16(acc[mi][2], a[0], a[1], a[2], a[3], f1[0], f1[2]);
                mma_bf16(acc[mi][3], a[0], a[1], a[2], a[3], f1[1], f1[3]);
            }
        }
        __syncthreads();
    }

    // epilogue: sigmoid + dot with W2 slice, reduce to per-row partials
    float w2v[8], bv[8];
    #pragma unroll
    for (int ni = 0; ni < 4; ni++) {
        int col = n0 + wn + ni * 8 + tig * 2;
        w2v[ni * 2]     = W2[col];
        w2v[ni * 2 + 1] = W2[col + 1];
        bv [ni * 2]     = bias[col];
        bv [ni * 2 + 1] = bias[col + 1];
    }
    float part[8];
    #pragma unroll
    for (int j = 0; j < 8; j++) part[j] = 0.f;
    #pragma unroll
    for (int mi = 0; mi < 4; mi++)
        #pragma unroll
        for (int ni = 0; ni < 4; ni++) {
            float b0 = bv[ni * 2], b1v = bv[ni * 2 + 1];
            float w0 = w2v[ni * 2], w1 = w2v[ni * 2 + 1];
            part[mi * 2]     += sigma(acc[mi][ni][0] + b0) * w0
                              + sigma(acc[mi][ni][1] + b1v) * w1;
            part[mi * 2 + 1] += sigma(acc[mi][ni][2] + b0) * w0
                              + sigma(acc[mi][ni][3] + b1v) * w1;
        }
    #pragma unroll
    for (int j = 0; j < 8; j++) {
        part[j] += __shfl_xor_sync(0xffffffffu, part[j], 1);
        part[j] += __shfl_xor_sync(0xffffffffu, part[j], 2);
    }
    // reuse smem (all stages consumed; last __syncthreads already passed)
    float* sP = (float*)smx;      // [4 wn-groups][128 rows]
    if (tig == 0) {
        #pragma unroll
        for (int mi = 0; mi < 4; mi++) {
            int rl = wm + mi * 16 + g;
            sP[(warp >> 1) * 128 + rl]     = part[mi * 2];
            sP[(warp >> 1) * 128 + rl + 8] = part[mi * 2 + 1];
        }
    }
    __syncthreads();
    if (t < 128) {
        float s = sP[t] + sP[128 + t] + sP[256 + t] + sP[384 + t];
        g_P[(size_t)blockIdx.y * BATCH + m0 + t] = s;
    }
}

// ---------------- K4: final combine ----------------
__global__ void k_fin(const float* __restrict__ b2, float* __restrict__ out)
{
    int b = blockIdx.x * blockDim.x + threadIdx.x;
    if (b >= BATCH) return;
    out[b] = sigmoidf(g_P[b] + g_P[BATCH + b] + b2[0]);
}

// ---------------- host: numpy-legacy MT19937 graph reconstruction ----------------
namespace {
struct MT { uint32_t mt[624]; int idx; };
static void mt_seed(MT& s, uint32_t seed) {
    s.mt[0] = seed;
    for (int i = 1; i < 624; i++)
        s.mt[i] = 1812433253u * (s.mt[i-1] ^ (s.mt[i-1] >> 30)) + (uint32_t)i;
    s.idx = 624;
}
static uint32_t mt_next(MT& s) {
    if (s.idx >= 624) {
        for (int i = 0; i < 624; i++) {
            uint32_t y = (s.mt[i] & 0x80000000u) | (s.mt[(i+1) % 624] & 0x7fffffffu);
            s.mt[i] = s.mt[(i+397) % 624] ^ (y >> 1) ^ ((y & 1u) ? 0x9908b0dfu : 0u);
        }
        s.idx = 0;
    }
    uint32_t y = s.mt[s.idx++];
    y ^= y >> 11;
    y ^= (y << 7)  & 0x9d2c5680u;
    y ^= (y << 15) & 0xefc60000u;
    y ^= y >> 18;
    return y;
}
static uint32_t draw_bounded(MT& s, uint32_t rng) {
    uint32_t mask = rng; mask |= mask >> 1; mask |= mask >> 2; mask |= mask >> 4;
    mask |= mask >> 8; mask |= mask >> 16;
    uint32_t v;
    do { v = mt_next(s) & mask; } while (v > rng);
    return v;
}
static void build_graph(Sched& sc, int& E) {
    MT mt; mt_seed(mt, 0u);
    int off = 0;
    int level[NC];
    for (int k = 0; k < NC; k++) {
        int l = 0;
        if (k > 0) {
            int hi = (k < 3 ? k : 3) + 1;
            l = (int)draw_bounded(mt, (uint32_t)(hi - 1));
        }
        int preds[3] = {0, 0, 0};
        if (l > 0) {
            int arr[NC];
            for (int i = 0; i < k; i++) arr[i] = i;
            for (int i = k - 1; i >= 1; i--) {
                uint32_t j = draw_bounded(mt, (uint32_t)i);
                int tmp = arr[i]; arr[i] = arr[(int)j]; arr[(int)j] = tmp;
            }
            for (int jj = 0; jj < l; jj++) preds[jj] = arr[jj];
            for (int a = 0; a < l; a++)
                for (int b2_ = a + 1; b2_ < l; b2_++)
                    if (preds[b2_] < preds[a]) { int tm = preds[a]; preds[a] = preds[b2_]; preds[b2_] = tm; }
        }
        sc.lp[k] = (unsigned char)l;
        sc.off[k] = (unsigned short)off;
        sc.invl[k] = (l > 0) ? 1.0f / (float)l : 1.0f;
        for (int jj = 0; jj < 3; jj++) sc.pred[k][jj] = (unsigned char)(jj < l ? preds[jj] : 0);
        int lvl = 0;
        for (int jj = 0; jj < l; jj++) {
            int pl = level[preds[jj]] + 1;
            if (pl > lvl) lvl = pl;
        }
        level[k] = lvl;
        off += l;
    }
    E = off;
    int maxlvl = 0;
    for (int k = 0; k < NC; k++) if (level[k] > maxlvl) maxlvl = level[k];
    sc.nLvl = maxlvl + 1;
    int pos = 0;
    for (int lv = 0; lv <= maxlvl; lv++) {
        sc.lvlStart[lv] = (short)pos;
        for (int k = 0; k < NC; k++)
            if (level[k] == lv) sc.order[pos++] = (unsigned char)k;
    }
    sc.lvlStart[maxlvl + 1] = (short)pos;
}
} // namespace

extern "C" void kernel_launch(void* const* d_in, const int* in_sizes, int n_in,
                              void* d_out, int out_size)
{
    Sched sc; int E;
    build_graph(sc, E);

    const int*   uid    = (const int*)  d_in[0];
    const int*   qid    = (const int*)  d_in[1];
    const float* priori = (const float*)d_in[2];
    const float* cpd    = (const float*)d_in[3];
    const float* cnd    = (const float*)d_in[4];
    const float* idiff  = (const float*)d_in[5];
    const float* idisc  = (const float*)d_in[6];
    const float* qt     = (const float*)d_in[7];
    const float* bu     = (const float*)d_in[9];
    const float* bi     = (const float*)d_in[11];
    const float* b1     = (const float*)d_in[13];
    const float* W2     = (const float*)d_in[14];
    const float* b2     = (const float*)d_in[15];
    float* out = (float*)d_out;

    int Ein = in_sizes[3] / NUM_USER;
    if (Ein > 0 && Ein <= MAXE) E = Ein;

    static bool attr_done = false;
    if (!attr_done) {
        cudaFuncSetAttribute(k_factor, cudaFuncAttributeMaxDynamicSharedMemorySize, SMEM_FACTOR);
        cudaFuncSetAttribute(k_mlp,    cudaFuncAttributeMaxDynamicSharedMemorySize, SMEM_MLP);
        attr_done = true;
    }

    k_pre<<<(BATCH * KW + 255) / 256, 256>>>(qid, idiff, idisc, qt,
                                             (const float*)d_in[8], (const float*)d_in[10],
                                             (const float*)d_in[12]);

    k_mastery2<<<BATCH / WPB, WPB * 32>>>(uid, qid, priori, cpd, cnd, qt, sc, E);

    k_factor<<<dim3(BATCH / 128, DH / 64), 256, SMEM_FACTOR>>>(bu, bi);

    k_mlp<<<dim3(BATCH / 128, H2 / 128), 256, SMEM_MLP>>>(b1, W2);

    k_fin<<<(BATCH + 255) / 256, 256>>>(b2, out);
}